// round 15
// baseline (speedup 1.0000x reference)
#include <cuda_runtime.h>
#include <cuda_fp16.h>
#include <math.h>
#include <stdint.h>

typedef long long ll;

// ---------------------------------------------------------------------------
// Problem constants
// ---------------------------------------------------------------------------
#define Bz   8
#define Tt   512
#define Dd   768
#define Hh   8
#define HD   96
#define NEXP 4
#define RH   128
#define D3   (3*Dd)     // 2304
#define D4   (4*Dd)     // 3072
#define SCALE_V (0.10206207261596575f)  // 1/sqrt(96)
#define LN_EPS 1e-5f

// ---------------------------------------------------------------------------
// Scratch (static device arrays -- no allocation allowed)
// ---------------------------------------------------------------------------
__device__ __half g_qkvh  [(ll)Bz*Tt*D3];
__device__ __half g_qkv2h [(ll)Bz*Tt*D3];
__device__ __half g_xnh   [(ll)Bz*Tt*Dd];
__device__ __half g_xth   [(ll)Bz*Tt*Dd];
__device__ float  g_xtf   [(ll)Bz*Tt*Dd];
__device__ __half g_attno [(ll)Bz*Tt*Dd];
__device__ __half g_attno2[(ll)Bz*Tt*Dd];
__device__ __half g_spout [(ll)Bz*Tt*Dd];
__device__ __half g_tpout [(ll)Bz*Tt*Dd];
__device__ float  g_x1    [(ll)Bz*Tt*Dd];
__device__ __half g_hid   [(ll)Bz*Tt*D4];
__device__ int    g_idx   [16];
__device__ float  g_btp   [(ll)NEXP*D3];
// fp16 weight copies
__device__ __half g_wspqkv[(ll)NEXP*D3*Dd];
__device__ __half g_wspo  [(ll)NEXP*Dd*Dd];
__device__ __half g_wtpqkv[(ll)NEXP*D3*Dd];   // packed q/k/v
__device__ __half g_wtpo  [(ll)NEXP*Dd*Dd];
__device__ __half g_wcqkv [(ll)3*Dd*Dd];
__device__ __half g_wco   [(ll)Dd*Dd];
__device__ __half g_wm1   [(ll)D4*Dd];
__device__ __half g_wm2   [(ll)Dd*D4];

__device__ __forceinline__ float gelu_exact(float v) {
    return 0.5f * v * (1.0f + erff(v * 0.70710678118654752f));
}
__device__ __forceinline__ uint32_t smem_u32(const void* p) {
    return (uint32_t)__cvta_generic_to_shared(p);
}

#define CP_ASYNC_16(dst_u32, src_ptr) \
    asm volatile("cp.async.cg.shared.global [%0], [%1], 16;\n" :: "r"(dst_u32), "l"(src_ptr))
#define CP_COMMIT() asm volatile("cp.async.commit_group;\n")
#define CP_WAIT(N)  asm volatile("cp.async.wait_group %0;\n" :: "n"(N))

__device__ __forceinline__ void ldsm_x4(uint32_t* r, uint32_t addr) {
    asm volatile("ldmatrix.sync.aligned.m8n8.x4.shared.b16 {%0,%1,%2,%3}, [%4];"
        : "=r"(r[0]), "=r"(r[1]), "=r"(r[2]), "=r"(r[3]) : "r"(addr));
}
__device__ __forceinline__ void ldsm_x4_t(uint32_t* r, uint32_t addr) {
    asm volatile("ldmatrix.sync.aligned.m8n8.x4.trans.shared.b16 {%0,%1,%2,%3}, [%4];"
        : "=r"(r[0]), "=r"(r[1]), "=r"(r[2]), "=r"(r[3]) : "r"(addr));
}
__device__ __forceinline__ void mma_fp16(float* c, const uint32_t* a, const uint32_t* b) {
    asm volatile(
        "mma.sync.aligned.m16n8k16.row.col.f32.f16.f16.f32 "
        "{%0,%1,%2,%3}, {%4,%5,%6,%7}, {%8,%9}, {%0,%1,%2,%3};"
        : "+f"(c[0]), "+f"(c[1]), "+f"(c[2]), "+f"(c[3])
        : "r"(a[0]), "r"(a[1]), "r"(a[2]), "r"(a[3]),
          "r"(b[0]), "r"(b[1]));
}
__device__ __forceinline__ uint32_t packh2(float a, float b) {
    __half2 h = __floats2half2_rn(a, b);
    return *(uint32_t*)&h;
}

// ---------------------------------------------------------------------------
// Mega weight convert (16 elems / thread) + temporal qkv packing
// ---------------------------------------------------------------------------
#define SEG_SPQKV ((ll)NEXP*D3*Dd)
#define SEG_DD    ((ll)NEXP*Dd*Dd)
#define SEG_CQKV  ((ll)3*Dd*Dd)
#define SEG_CO    ((ll)Dd*Dd)
#define SEG_M     ((ll)D4*Dd)
#define CONV_TOTAL (SEG_SPQKV + SEG_DD + 3*SEG_DD + SEG_DD + SEG_CQKV + SEG_CO + 2*SEG_M)

__device__ __forceinline__ void cvt16(__half* d, const float* s) {
    float4 v0 = *(const float4*)(s);
    float4 v1 = *(const float4*)(s + 4);
    float4 v2 = *(const float4*)(s + 8);
    float4 v3 = *(const float4*)(s + 12);
    *(__half2*)(d)      = __floats2half2_rn(v0.x, v0.y);
    *(__half2*)(d + 2)  = __floats2half2_rn(v0.z, v0.w);
    *(__half2*)(d + 4)  = __floats2half2_rn(v1.x, v1.y);
    *(__half2*)(d + 6)  = __floats2half2_rn(v1.z, v1.w);
    *(__half2*)(d + 8)  = __floats2half2_rn(v2.x, v2.y);
    *(__half2*)(d + 10) = __floats2half2_rn(v2.z, v2.w);
    *(__half2*)(d + 12) = __floats2half2_rn(v3.x, v3.y);
    *(__half2*)(d + 14) = __floats2half2_rn(v3.z, v3.w);
}

__global__ __launch_bounds__(256) void convert_all_kernel(
    const float* __restrict__ spqkv, const float* __restrict__ spo,
    const float* __restrict__ tq, const float* __restrict__ tk,
    const float* __restrict__ tv, const float* __restrict__ to,
    const float* __restrict__ cqkv, const float* __restrict__ cwo,
    const float* __restrict__ m1, const float* __restrict__ m2)
{
    ll i = ((ll)blockIdx.x * 256 + threadIdx.x) * 16;
    if (i >= CONV_TOTAL) return;
    ll o = i;
    if (o < SEG_SPQKV) { cvt16(g_wspqkv + o, spqkv + o); return; }
    o -= SEG_SPQKV;
    if (o < SEG_DD)    { cvt16(g_wspo + o, spo + o); return; }
    o -= SEG_DD;
    if (o < SEG_DD) {
        ll e = o / SEG_CO, rem = o - e * SEG_CO;
        cvt16(g_wtpqkv + e * ((ll)D3*Dd) + rem, tq + o); return;
    }
    o -= SEG_DD;
    if (o < SEG_DD) {
        ll e = o / SEG_CO, rem = o - e * SEG_CO;
        cvt16(g_wtpqkv + e * ((ll)D3*Dd) + (ll)Dd*Dd + rem, tk + o); return;
    }
    o -= SEG_DD;
    if (o < SEG_DD) {
        ll e = o / SEG_CO, rem = o - e * SEG_CO;
        cvt16(g_wtpqkv + e * ((ll)D3*Dd) + (ll)2*Dd*Dd + rem, tv + o); return;
    }
    o -= SEG_DD;
    if (o < SEG_DD)   { cvt16(g_wtpo + o, to + o); return; }
    o -= SEG_DD;
    if (o < SEG_CQKV) { cvt16(g_wcqkv + o, cqkv + o); return; }
    o -= SEG_CQKV;
    if (o < SEG_CO)   { cvt16(g_wco + o, cwo + o); return; }
    o -= SEG_CO;
    if (o < SEG_M)    { cvt16(g_wm1 + o, m1 + o); return; }
    o -= SEG_M;
    cvt16(g_wm2 + o, m2 + o);
}

__global__ void pack_btp_kernel(const float* __restrict__ bq,
                                const float* __restrict__ bk,
                                const float* __restrict__ bv)
{
    int i = blockIdx.x * 256 + threadIdx.x;
    if (i >= NEXP * D3) return;
    int e = i / D3, j = i - e * D3;
    float v = (j < Dd) ? bq[e*Dd + j] : (j < 2*Dd) ? bk[e*Dd + j - Dd] : bv[e*Dd + j - 2*Dd];
    g_btp[i] = v;
}

// ---------------------------------------------------------------------------
// Router
// ---------------------------------------------------------------------------
__global__ void router_kernel(const float* __restrict__ x,
                              const float* __restrict__ w1, const float* __restrict__ b1,
                              const float* __restrict__ w2, const float* __restrict__ b2,
                              int* __restrict__ idx_s, int* __restrict__ idx_t)
{
    __shared__ float xm[Dd];
    __shared__ float hbuf[RH];
    __shared__ float lg[8];
    int b = blockIdx.x;
    int d = threadIdx.x;
    const float* xb = x + (ll)b * Tt * Dd;
    float s = 0.f;
    for (int t = 0; t < Tt; t++) s += xb[(ll)t * Dd + d];
    xm[d] = s * (1.0f / Tt);
    __syncthreads();
    if (d < RH) {
        float a = b1[d];
        const float* wr = w1 + (ll)d * Dd;
        for (int k = 0; k < Dd; k++) a += xm[k] * wr[k];
        hbuf[d] = gelu_exact(a);
    }
    __syncthreads();
    if (d < 8) {
        float a = b2[d];
        const float* wr = w2 + d * RH;
        for (int k = 0; k < RH; k++) a += hbuf[k] * wr[k];
        lg[d] = a;
    }
    __syncthreads();
    if (d == 0) {
        int is = 0; for (int i = 1; i < NEXP; i++) if (lg[i] > lg[is]) is = i;
        int it = 0; for (int i = 1; i < NEXP; i++) if (lg[NEXP+i] > lg[NEXP+it]) it = i;
        idx_s[b] = is;
        idx_t[b] = it;
    }
}

// ---------------------------------------------------------------------------
// Fused dual-output LayerNorm (validated R14)
// ---------------------------------------------------------------------------
__global__ __launch_bounds__(256) void ln_dual_kernel(const float* __restrict__ x,
    const float* __restrict__ g0, const float* __restrict__ b0,
    __half* __restrict__ yh0,
    const float* __restrict__ g1, const float* __restrict__ b1,
    __half* __restrict__ yh1, float* __restrict__ yf1)
{
    __shared__ float2 sw[8];
    ll row = blockIdx.x;
    int t = threadIdx.x, lane = t & 31, wid = t >> 5;
    const float* xr = x + row * Dd;
    float a0 = xr[t], a1 = xr[t+256], a2 = xr[t+512];
    float s = a0 + a1 + a2;
    float s2 = a0*a0 + a1*a1 + a2*a2;
    #pragma unroll
    for (int o = 16; o; o >>= 1) {
        s  += __shfl_xor_sync(0xFFFFFFFFu, s, o);
        s2 += __shfl_xor_sync(0xFFFFFFFFu, s2, o);
    }
    if (lane == 0) sw[wid] = make_float2(s, s2);
    __syncthreads();
    if (t < 8) {
        float2 v = sw[t];
        float u = v.x, u2 = v.y;
        #pragma unroll
        for (int o = 4; o; o >>= 1) {
            u  += __shfl_xor_sync(0xFFu, u, o);
            u2 += __shfl_xor_sync(0xFFu, u2, o);
        }
        if (t == 0) sw[0] = make_float2(u, u2);
    }
    __syncthreads();
    float2 tot = sw[0];
    float mean = tot.x * (1.0f / Dd);
    float var = tot.y * (1.0f / Dd) - mean * mean;
    float inv = rsqrtf(var + LN_EPS);
    float n0 = (a0 - mean) * inv;
    float n1 = (a1 - mean) * inv;
    float n2 = (a2 - mean) * inv;
    {
        float v0 = n0 * g0[t]     + b0[t];
        float v1 = n1 * g0[t+256] + b0[t+256];
        float v2 = n2 * g0[t+512] + b0[t+512];
        __half* yr = yh0 + row * Dd;
        yr[t]     = __float2half_rn(v0);
        yr[t+256] = __float2half_rn(v1);
        yr[t+512] = __float2half_rn(v2);
    }
    {
        float v0 = n0 * g1[t]     + b1[t];
        float v1 = n1 * g1[t+256] + b1[t+256];
        float v2 = n2 * g1[t+512] + b1[t+512];
        __half* yr = yh1 + row * Dd;
        yr[t]     = __float2half_rn(v0);
        yr[t+256] = __float2half_rn(v1);
        yr[t+512] = __float2half_rn(v2);
        float* yfr = yf1 + row * Dd;
        yfr[t] = v0; yfr[t+256] = v1; yfr[t+512] = v2;
    }
}

// Single-set LN (MLP)
__global__ __launch_bounds__(256) void ln_kernel(const float* __restrict__ x,
    const float* __restrict__ g, const float* __restrict__ bb,
    __half* __restrict__ yh)
{
    __shared__ float2 sw[8];
    ll row = blockIdx.x;
    int t = threadIdx.x, lane = t & 31, wid = t >> 5;
    const float* xr = x + row * Dd;
    float a0 = xr[t], a1 = xr[t+256], a2 = xr[t+512];
    float s = a0 + a1 + a2;
    float s2 = a0*a0 + a1*a1 + a2*a2;
    #pragma unroll
    for (int o = 16; o; o >>= 1) {
        s  += __shfl_xor_sync(0xFFFFFFFFu, s, o);
        s2 += __shfl_xor_sync(0xFFFFFFFFu, s2, o);
    }
    if (lane == 0) sw[wid] = make_float2(s, s2);
    __syncthreads();
    if (t < 8) {
        float2 v = sw[t];
        float u = v.x, u2 = v.y;
        #pragma unroll
        for (int o = 4; o; o >>= 1) {
            u  += __shfl_xor_sync(0xFFu, u, o);
            u2 += __shfl_xor_sync(0xFFu, u2, o);
        }
        if (t == 0) sw[0] = make_float2(u, u2);
    }
    __syncthreads();
    float2 tot = sw[0];
    float mean = tot.x * (1.0f / Dd);
    float var = tot.y * (1.0f / Dd) - mean * mean;
    float inv = rsqrtf(var + LN_EPS);
    __half* yr = yh + row * Dd;
    yr[t]     = __float2half_rn((a0 - mean) * inv * g[t]     + bb[t]);
    yr[t+256] = __float2half_rn((a1 - mean) * inv * g[t+256] + bb[t+256]);
    yr[t+512] = __float2half_rn((a2 - mean) * inv * g[t+512] + bb[t+512]);
}

// ---------------------------------------------------------------------------
// Flash attention (dual-set): 256 threads, 128 queries/block (validated R8)
// ---------------------------------------------------------------------------
#define FL_KLD  104
#define FL_TILE (128 * FL_KLD)
#define FL_TILEB (FL_TILE * 2)
#define FL_SMEM (3 * FL_TILEB)         // 79872

__device__ __forceinline__ void fl_load_tile(const __half* gbase, int row0,
                                             __half* dstsm, int cr, int cc)
{
    #pragma unroll
    for (int rp = 0; rp < 2; rp++) {
        int r = rp * 64 + cr;
        const __half* src = gbase + (ll)(row0 + r) * D3 + cc;
        uint32_t dst = smem_u32(dstsm) + (uint32_t)((r * FL_KLD + cc) * 2);
        CP_ASYNC_16(dst,      src);
        CP_ASYNC_16(dst + 16, src + 8);
        CP_ASYNC_16(dst + 32, src + 16);
    }
}

__global__ __launch_bounds__(256, 1) void flash_kernel(
    const __half* __restrict__ QKVa, __half* __restrict__ Oa, int causalA,
    const __half* __restrict__ QKVb, __half* __restrict__ Ob, int causalB)
{
    extern __shared__ __half fsm[];
    __half* Ksm = fsm;
    __half* Vsm = fsm + FL_TILE;

    int z = blockIdx.z;
    const __half* QKV; __half* O; int causal; int b;
    if (z < Bz) { QKV = QKVa; O = Oa; causal = causalA; b = z; }
    else        { QKV = QKVb; O = Ob; causal = causalB; b = z - Bz; }

    int qt = blockIdx.x, h = blockIdx.y;
    int q0 = qt * 128;
    int tid = threadIdx.x, lane = tid & 31, w = tid >> 5;
    int g = lane >> 2, t4 = lane & 3;

    const __half* Qg = QKV + (ll)b * (Tt * D3) + (ll)q0 * D3 + h * HD;
    const __half* Kg = QKV + (ll)b * (Tt * D3) + Dd + h * HD;
    const __half* Vg = Kg + Dd;

    int cr = tid >> 2;
    int cc = (tid & 3) * 24;

    #pragma unroll
    for (int rp = 0; rp < 2; rp++) {
        int r = rp * 64 + cr;
        const __half* src = Qg + (ll)r * D3 + cc;
        uint32_t dst = smem_u32(Ksm) + (uint32_t)((r * FL_KLD + cc) * 2);
        CP_ASYNC_16(dst,      src);
        CP_ASYNC_16(dst + 16, src + 8);
        CP_ASYNC_16(dst + 32, src + 16);
    }
    CP_COMMIT(); CP_WAIT(0);
    __syncthreads();

    uint32_t qfr[6][4];
    {
        uint32_t aBase = smem_u32(Ksm) +
            (uint32_t)(((((lane & 15) + w * 16)) * FL_KLD + ((lane >> 4) << 3)) * 2);
        #pragma unroll
        for (int ks = 0; ks < 6; ks++) ldsm_x4(qfr[ks], aBase + ks * 32);
    }
    __syncthreads();

    int nk = causal ? (q0 / 128 + 1) : (Tt / 128);

    fl_load_tile(Kg, 0, Ksm, cr, cc);
    fl_load_tile(Vg, 0, Vsm, cr, cc);
    CP_COMMIT();

    float mrow[2] = {-1e30f, -1e30f};
    float lrow[2] = {0.f, 0.f};
    float oacc[12][4];
    #pragma unroll
    for (int j = 0; j < 12; j++)
        #pragma unroll
        for (int q = 0; q < 4; q++) oacc[j][q] = 0.f;

    uint32_t kBase = smem_u32(Ksm) +
        (uint32_t)(((((lane & 7) + ((lane >> 4) << 3))) * FL_KLD + (((lane >> 3) & 1) << 3)) * 2);
    uint32_t vBase = smem_u32(Vsm) +
        (uint32_t)(((((lane & 7) + (((lane >> 3) & 1) << 3))) * FL_KLD + ((lane >> 4) << 3)) * 2);

    for (int kt = 0; kt < nk; kt++) {
        CP_WAIT(0);
        __syncthreads();
        int cur = kt & 1;

        float s[16][4];
        #pragma unroll
        for (int j = 0; j < 16; j++)
            #pragma unroll
            for (int q = 0; q < 4; q++) s[j][q] = 0.f;

        #pragma unroll
        for (int ks = 0; ks < 6; ks++) {
            #pragma unroll
            for (int jp = 0; jp < 8; jp++) {
                uint32_t rb[4];
                ldsm_x4(rb, kBase + jp * (16 * FL_KLD * 2) + ks * 32);
                mma_fp16(s[2*jp],   qfr[ks], rb);
                mma_fp16(s[2*jp+1], qfr[ks], rb + 2);
            }
        }

        bool domask = causal && (kt * 128 + 127 > q0);
        #pragma unroll
        for (int j = 0; j < 16; j++)
            #pragma unroll
            for (int q = 0; q < 4; q++) s[j][q] *= SCALE_V;
        if (domask) {
            int rbase = q0 + w * 16 + g;
            #pragma unroll
            for (int j = 0; j < 16; j++) {
                int key0 = kt * 128 + j * 8 + 2 * t4;
                #pragma unroll
                for (int q = 0; q < 4; q++) {
                    int key = key0 + (q & 1);
                    int row = rbase + ((q >> 1) << 3);
                    if (key > row) s[j][q] = -1e30f;
                }
            }
        }

        uint32_t p[8][4];
        #pragma unroll
        for (int hf = 0; hf < 2; hf++) {
            float mx = -1e30f;
            #pragma unroll
            for (int j = 0; j < 16; j++)
                mx = fmaxf(mx, fmaxf(s[j][hf*2], s[j][hf*2+1]));
            mx = fmaxf(mx, __shfl_xor_sync(0xFFFFFFFFu, mx, 1));
            mx = fmaxf(mx, __shfl_xor_sync(0xFFFFFFFFu, mx, 2));
            float mnew = fmaxf(mrow[hf], mx);
            float corr = expf(mrow[hf] - mnew);
            mrow[hf] = mnew;
            float rsum = 0.f;
            #pragma unroll
            for (int j = 0; j < 16; j++) {
                float e0 = expf(s[j][hf*2]   - mnew);
                float e1 = expf(s[j][hf*2+1] - mnew);
                s[j][hf*2] = e0; s[j][hf*2+1] = e1;
                rsum += e0 + e1;
            }
            rsum += __shfl_xor_sync(0xFFFFFFFFu, rsum, 1);
            rsum += __shfl_xor_sync(0xFFFFFFFFu, rsum, 2);
            lrow[hf] = lrow[hf] * corr + rsum;
            #pragma unroll
            for (int j = 0; j < 12; j++) {
                oacc[j][hf*2]   *= corr;
                oacc[j][hf*2+1] *= corr;
            }
        }
        #pragma unroll
        for (int ksv = 0; ksv < 8; ksv++) {
            p[ksv][0] = packh2(s[2*ksv][0],   s[2*ksv][1]);
            p[ksv][1] = packh2(s[2*ksv][2],   s[2*ksv][3]);
            p[ksv][2] = packh2(s[2*ksv+1][0], s[2*ksv+1][1]);
            p[ksv][3] = packh2(s[2*ksv+1][2], s[2*ksv+1][3]);
        }

        __syncthreads();
        if (kt + 1 < nk) {
            fl_load_tile(Kg, (kt+1) * 128, Ksm, cr, cc);
            fl_load_tile(Vg, (kt+1) * 128, Vsm + (1 - cur) * FL_TILE, cr, cc);
            CP_COMMIT();
        }

        uint32_t vb = vBase + cur * FL_TILEB;
        #pragma unroll
        for (int ksv = 0; ksv < 8; ksv++) {
            #pragma unroll
            for (int jp = 0; jp < 6; jp++) {
                uint32_t rb[4];
                ldsm_x4_t(rb, vb + ksv * (16 * FL_KLD * 2) + jp * 32);
                mma_fp16(oacc[2*jp],   p[ksv], rb);
                mma_fp16(oacc[2*jp+1], p[ksv], rb + 2);
            }
        }
    }

    #pragma unroll
    for (int hf = 0; hf < 2; hf++) {
        float inv = 1.f / lrow[hf];
        int r = q0 + w * 16 + g + hf * 8;
        __half* orow = O + (ll)b * (Tt * Dd) + (ll)r * Dd + h * HD;
        #pragma unroll
        for (int j = 0; j < 12; j++) {
            *(__half2*)(orow + j * 8 + 2 * t4) =
                __floats2half2_rn(oacc[j][hf*2] * inv, oacc[j][hf*2+1] * inv);
        }
    }
}

// ---------------------------------------------------------------------------
// FP16 NT GEMM engine: BK=64 (half the per-tile barriers), 2-stage cp.async,
// 128 threads, 4 warps (2m x 2n), warp tile 64x64, block 128x128, 2 CTA/SM.
// ---------------------------------------------------------------------------
#define ALD   72                       // 64 + 8 pad halfs; row stride 144B
#define ASTG  (128 * ALD)
#define ASTGB (ASTG * 2)               // 18432 B
#define GEMM_SMEM (2 * 2 * ASTGB)      // 73728 B (A+W, 2 stages)

struct GemmP {
    const __half* A;     // [rows, Kd], batch stride Tt*Kd
    const __half* W;     // [N, Kd] (+ expert stride)
    ll esW;
    const int* eidx;
    const float* bias;   // fp32 [N] (+ expert stride esBias)
    int esBias;
    const float* res;    // fp32 [rows, Dd], batch stride Tt*Dd
    void* C;             // ldc, batch stride Tt*ldc
    int ldc;
    int cHalf;
    int Kd;
    int act;
};

__device__ __forceinline__ void gemm_copy_tile(
    const __half* a, const __half* w, uint32_t dA, uint32_t dW, ll rowStep)
{
    #pragma unroll
    for (int rp = 0; rp < 4; rp++) {
        const __half* as = a + rp * rowStep;
        const __half* ws = w + rp * rowStep;
        uint32_t oa = dA + rp * (32 * ALD * 2);
        uint32_t ow = dW + rp * (32 * ALD * 2);
        CP_ASYNC_16(oa,      as);
        CP_ASYNC_16(oa + 16, as + 8);
        CP_ASYNC_16(ow,      ws);
        CP_ASYNC_16(ow + 16, ws + 8);
    }
}

__device__ __forceinline__ void gemm_body(const GemmP p, int b, int m0, int n0)
{
    extern __shared__ __half hsm[];
    __half* Asm = hsm;                // 2 stages
    __half* Wsm = hsm + 2 * ASTG;

    const __half* A = p.A + (ll)b * Tt * p.Kd;
    ll woff = 0;
    const float* biasp = p.bias;
    if (p.eidx) {
        int e = p.eidx[b];
        woff = (ll)e * p.esW;
        if (biasp) biasp += (ll)e * p.esBias;
    }
    const __half* W = p.W + woff;
    const float* res = p.res ? (p.res + (ll)b * (Tt * Dd)) : nullptr;

    int tid = threadIdx.x, lane = tid & 31, warp = tid >> 5;
    int wm = warp & 1, wn = warp >> 1;
    int wmb = wm * 64, wnb = wn * 64;
    int g = lane >> 2, t4 = lane & 3;

    // copy lanes: r0 0..31, c0 in {0,16,32,48} halfs (two 16B chunks each)
    int r0 = tid >> 2, c0 = (tid & 3) * 16;
    const __half* Ap = A + (ll)(m0 + r0) * p.Kd + c0;
    const __half* Wp = W + (ll)(n0 + r0) * p.Kd + c0;
    uint32_t dA = smem_u32(Asm) + (uint32_t)((r0 * ALD + c0) * 2);
    uint32_t dW = smem_u32(Wsm) + (uint32_t)((r0 * ALD + c0) * 2);
    ll rowStep = (ll)32 * p.Kd;

    float acc[4][8][4];
    #pragma unroll
    for (int i = 0; i < 4; i++)
        #pragma unroll
        for (int j = 0; j < 8; j++)
            #pragma unroll
            for (int q = 0; q < 4; q++) acc[i][j][q] = 0.f;

    uint32_t aBase = smem_u32(Asm) +
        (uint32_t)((((lane & 15) + wmb) * ALD + ((lane >> 4) << 3)) * 2);
    uint32_t bBase = smem_u32(Wsm) +
        (uint32_t)((((lane & 7) + ((lane >> 4) << 3) + wnb) * ALD + (((lane >> 3) & 1) << 3)) * 2);

    int kTiles = p.Kd >> 6;   // BK = 64

    // prologue: stage 0
    gemm_copy_tile(Ap, Wp, dA, dW, rowStep);
    CP_COMMIT();

    for (int kt = 0; kt < kTiles; kt++) {
        int cur = kt & 1;
        if (kt + 1 < kTiles) {
            int nxt = cur ^ 1;
            gemm_copy_tile(Ap + (kt + 1) * 64, Wp + (kt + 1) * 64,
                           dA + nxt * ASTGB, dW + nxt * ASTGB, rowStep);
            CP_COMMIT();
            CP_WAIT(1);
        } else {
            CP_WAIT(0);
        }
        __syncthreads();

        uint32_t sa = aBase + cur * ASTGB;
        uint32_t sb = bBase + cur * ASTGB;
        #pragma unroll
        for (int ks = 0; ks < 4; ks++) {
            uint32_t afr[4][4], bfr[8][2];
            #pragma unroll
            for (int im = 0; im < 4; im++)
                ldsm_x4(afr[im], sa + im * (16 * ALD * 2) + ks * 32);
            #pragma unroll
            for (int jp = 0; jp < 4; jp++) {
                uint32_t rb[4];
                ldsm_x4(rb, sb + jp * (16 * ALD * 2) + ks * 32);
                bfr[2*jp][0]   = rb[0]; bfr[2*jp][1]   = rb[1];
                bfr[2*jp+1][0] = rb[2]; bfr[2*jp+1][1] = rb[3];
            }
            #pragma unroll
            for (int im = 0; im < 4; im++)
                #pragma unroll
                for (int jn = 0; jn < 8; jn++)
                    mma_fp16(acc[im][jn], afr[im], bfr[jn]);
        }
        __syncthreads();
    }

    __half* Ch = (__half*)p.C;
    float*  Cf = (float*)p.C;
    ll cb = (ll)b * Tt * p.ldc;
    #pragma unroll
    for (int im = 0; im < 4; im++) {
        int rr0 = m0 + wmb + im * 16 + g;
        #pragma unroll
        for (int jn = 0; jn < 8; jn++) {
            int c = n0 + wnb + jn * 8 + 2 * t4;
            float bv0 = biasp ? biasp[c]     : 0.f;
            float bv1 = biasp ? biasp[c + 1] : 0.f;
            #pragma unroll
            for (int hf = 0; hf < 2; hf++) {
                int r = rr0 + hf * 8;
                float v0 = acc[im][jn][hf*2+0] + bv0;
                float v1 = acc[im][jn][hf*2+1] + bv1;
                if (p.act) { v0 = gelu_exact(v0); v1 = gelu_exact(v1); }
                if (res) {
                    const float* rp2 = res + (ll)r * Dd + c;
                    v0 += rp2[0]; v1 += rp2[1];
                }
                if (p.cHalf)
                    *(__half2*)(Ch + cb + (ll)r * p.ldc + c) = __floats2half2_rn(v0, v1);
                else
                    *(float2*)(Cf + cb + (ll)r * p.ldc + c) = make_float2(v0, v1);
            }
        }
    }
}

__global__ __launch_bounds__(128, 2) void hgemm_one(GemmP p) {
    gemm_body(p, blockIdx.z, blockIdx.y * 128, blockIdx.x * 128);
}
__global__ __launch_bounds__(128, 2) void hgemm_dualz(GemmP p0, GemmP p1) {
    int z = blockIdx.z;
    if (z < Bz) gemm_body(p0, z, blockIdx.y * 128, blockIdx.x * 128);
    else        gemm_body(p1, z - Bz, blockIdx.y * 128, blockIdx.x * 128);
}
__global__ __launch_bounds__(128, 2) void hgemm_dualx(GemmP p0, GemmP p1, int xsplit) {
    int xb = blockIdx.x;
    if (xb < xsplit) gemm_body(p0, blockIdx.z, blockIdx.y * 128, xb * 128);
    else             gemm_body(p1, blockIdx.z, blockIdx.y * 128, (xb - xsplit) * 128);
}

// ---------------------------------------------------------------------------
// Orchestration
// ---------------------------------------------------------------------------
extern "C" void kernel_launch(void* const* d_in, const int* in_sizes, int n_in,
                              void* d_out, int out_size)
{
    const float* x        = (const float*)d_in[0];
    const float* rw1      = (const float*)d_in[1];
    const float* rb1      = (const float*)d_in[2];
    const float* rw2      = (const float*)d_in[3];
    const float* rb2      = (const float*)d_in[4];
    const float* nsg      = (const float*)d_in[5];
    const float* nsb      = (const float*)d_in[6];
    const float* ntg      = (const float*)d_in[7];
    const float* ntb      = (const float*)d_in[8];
    const float* nmg      = (const float*)d_in[9];
    const float* nmb      = (const float*)d_in[10];
    const float* sp_wqkv  = (const float*)d_in[11];
    const float* sp_bqkv  = (const float*)d_in[12];
    const float* sp_wo    = (const float*)d_in[13];
    const float* sp_bo    = (const float*)d_in[14];
    const float* tp_wq    = (const float*)d_in[15];
    const float* tp_bq    = (const float*)d_in[16];
    const float* tp_wk    = (const float*)d_in[17];
    const float* tp_bk    = (const float*)d_in[18];
    const float* tp_wv    = (const float*)d_in[19];
    const float* tp_bv    = (const float*)d_in[20];
    const float* tp_wo    = (const float*)d_in[21];
    const float* tp_bo    = (const float*)d_in[22];
    const float* c_wqkv   = (const float*)d_in[23];
    const float* c_bqkv   = (const float*)d_in[24];
    const float* c_wo     = (const float*)d_in[25];
    const float* c_bo     = (const float*)d_in[26];
    const float* mlp_w1   = (const float*)d_in[27];
    const float* mlp_b1   = (const float*)d_in[28];
    const float* mlp_w2   = (const float*)d_in[29];
    const float* mlp_b2   = (const float*)d_in[30];
    float* out = (float*)d_out;

    static int attr_done = 0;
    if (!attr_done) {
        cudaFuncSetAttribute(hgemm_one,   cudaFuncAttributeMaxDynamicSharedMemorySize, GEMM_SMEM);
        cudaFuncSetAttribute(hgemm_dualz, cudaFuncAttributeMaxDynamicSharedMemorySize, GEMM_SMEM);
        cudaFuncSetAttribute(hgemm_dualx, cudaFuncAttributeMaxDynamicSharedMemorySize, GEMM_SMEM);
        cudaFuncSetAttribute(flash_kernel, cudaFuncAttributeMaxDynamicSharedMemorySize, FL_SMEM);
        attr_done = 1;
    }

    float *xtf, *x1, *btp;
    __half *qkv, *qkv2, *xnh, *xth, *attno, *attno2, *spout, *tpout, *hid;
    __half *wspqkv, *wspo, *wtpqkv, *wtpo, *wcqkv, *wco, *wm1, *wm2;
    int* idx;
    cudaGetSymbolAddress((void**)&qkv,    g_qkvh);
    cudaGetSymbolAddress((void**)&qkv2,   g_qkv2h);
    cudaGetSymbolAddress((void**)&xnh,    g_xnh);
    cudaGetSymbolAddress((void**)&xth,    g_xth);
    cudaGetSymbolAddress((void**)&xtf,    g_xtf);
    cudaGetSymbolAddress((void**)&attno,  g_attno);
    cudaGetSymbolAddress((void**)&attno2, g_attno2);
    cudaGetSymbolAddress((void**)&spout,  g_spout);
    cudaGetSymbolAddress((void**)&tpout,  g_tpout);
    cudaGetSymbolAddress((void**)&x1,     g_x1);
    cudaGetSymbolAddress((void**)&hid,    g_hid);
    cudaGetSymbolAddress((void**)&idx,    g_idx);
    cudaGetSymbolAddress((void**)&btp,    g_btp);
    cudaGetSymbolAddress((void**)&wspqkv, g_wspqkv);
    cudaGetSymbolAddress((void**)&wspo,   g_wspo);
    cudaGetSymbolAddress((void**)&wtpqkv, g_wtpqkv);
    cudaGetSymbolAddress((void**)&wtpo,   g_wtpo);
    cudaGetSymbolAddress((void**)&wcqkv,  g_wcqkv);
    cudaGetSymbolAddress((void**)&wco,    g_wco);
    cudaGetSymbolAddress((void**)&wm1,    g_wm1);
    cudaGetSymbolAddress((void**)&wm2,    g_wm2);

    // ---- weight conversion + bias packing + router ----
    {
        int blocks = (int)((CONV_TOTAL / 16 + 255) / 256);
        convert_all_kernel<<<blocks, 256>>>(sp_wqkv, sp_wo, tp_wq, tp_wk, tp_wv,
                                            tp_wo, c_wqkv, c_wo, mlp_w1, mlp_w2);
        pack_btp_kernel<<<(NEXP*D3 + 255)/256, 256>>>(tp_bq, tp_bk, tp_bv);
    }
    router_kernel<<<Bz, Dd>>>(x, rw1, rb1, rw2, rb2, idx, idx + 8);

    // ---- LN (spatial + temporal fused into ONE pass over x) ----
    ln_dual_kernel<<<4096, 256>>>(x, nsg, nsb, xnh, ntg, ntb, xth, xtf);

    // ---- QKV GEMMs (spatial + temporal fused) ----
    {
        GemmP p0 = { xnh, wspqkv, (ll)D3 * Dd, idx,     sp_bqkv, D3, nullptr, qkv,  D3, 1, Dd, 0 };
        GemmP p1 = { xth, wtpqkv, (ll)D3 * Dd, idx + 8, btp,     D3, nullptr, qkv2, D3, 1, Dd, 0 };
        hgemm_dualz<<<dim3(D3/128, Tt/128, 2*Bz), 128, GEMM_SMEM>>>(p0, p1);
    }

    // ---- flash (spatial non-causal + temporal causal fused) ----
    flash_kernel<<<dim3(Tt/128, Hh, 2*Bz), 256, FL_SMEM>>>(qkv, attno, 0, qkv2, attno2, 1);

    // ---- output projections (spatial + temporal fused) ----
    {
        GemmP p0 = { attno,  wspo, (ll)Dd * Dd, idx,     sp_bo, Dd, nullptr, spout, Dd, 1, Dd, 0 };
        GemmP p1 = { attno2, wtpo, (ll)Dd * Dd, idx + 8, tp_bo, Dd, xtf,     tpout, Dd, 1, Dd, 0 };
        hgemm_dualz<<<dim3(Dd/128, Tt/128, 2*Bz), 128, GEMM_SMEM>>>(p0, p1);
    }

    // ---- cross q (from spout) + cross kv (from tpout) fused over grid.x ----
    {
        GemmP p0 = { spout, wcqkv,                0, nullptr, c_bqkv,      0, nullptr, qkv,      D3, 1, Dd, 0 };
        GemmP p1 = { tpout, wcqkv + (ll)Dd * Dd,  0, nullptr, c_bqkv + Dd, 0, nullptr, qkv + Dd, D3, 1, Dd, 0 };
        hgemm_dualx<<<dim3(18, Tt/128, Bz), 128, GEMM_SMEM>>>(p0, p1, 6);
    }

    // ---- cross flash ----
    flash_kernel<<<dim3(Tt/128, Hh, Bz), 256, FL_SMEM>>>(qkv, attno, 0, qkv, attno, 0);

    // ---- cross out: x1 = x + attno @ wco^T + c_bo (fp32) ----
    {
        GemmP p = { attno, wco, 0, nullptr, c_bo, 0, x, x1, Dd, 0, Dd, 0 };
        hgemm_one<<<dim3(Dd/128, Tt/128, Bz), 128, GEMM_SMEM>>>(p);
    }

    // ---- MLP ----
    ln_kernel<<<4096, 256>>>(x1, nmg, nmb, xnh);

    {
        GemmP p = { xnh, wm1, 0, nullptr, mlp_b1, 0, nullptr, hid, D4, 1, Dd, 1 };
        hgemm_one<<<dim3(D4/128, (Bz*Tt)/128, 1), 128, GEMM_SMEM>>>(p);
    }
    {
        GemmP p = { hid, wm2, 0, nullptr, mlp_b2, 0, x1, out, Dd, 0, D4, 0 };
        hgemm_one<<<dim3(Dd/128, (Bz*Tt)/128, 1), 128, GEMM_SMEM>>>(p);
    }
}

// round 16
// speedup vs baseline: 1.0719x; 1.0719x over previous
#include <cuda_runtime.h>
#include <cuda_fp16.h>
#include <math.h>
#include <stdint.h>

typedef long long ll;

// ---------------------------------------------------------------------------
// Problem constants
// ---------------------------------------------------------------------------
#define Bz   8
#define Tt   512
#define Dd   768
#define Hh   8
#define HD   96
#define NEXP 4
#define RH   128
#define D3   (3*Dd)     // 2304
#define D4   (4*Dd)     // 3072
#define SCALE_V (0.10206207261596575f)  // 1/sqrt(96)
#define LN_EPS 1e-5f
#define STAGES 4

// ---------------------------------------------------------------------------
// Scratch (static device arrays -- no allocation allowed)
// ---------------------------------------------------------------------------
__device__ __half g_qkvh  [(ll)Bz*Tt*D3];
__device__ __half g_qkv2h [(ll)Bz*Tt*D3];
__device__ __half g_xnh   [(ll)Bz*Tt*Dd];
__device__ __half g_xth   [(ll)Bz*Tt*Dd];
__device__ float  g_xtf   [(ll)Bz*Tt*Dd];
__device__ __half g_attno [(ll)Bz*Tt*Dd];
__device__ __half g_attno2[(ll)Bz*Tt*Dd];
__device__ __half g_spout [(ll)Bz*Tt*Dd];
__device__ __half g_tpout [(ll)Bz*Tt*Dd];
__device__ float  g_x1    [(ll)Bz*Tt*Dd];
__device__ __half g_hid   [(ll)Bz*Tt*D4];
__device__ int    g_idx   [16];
__device__ float  g_btp   [(ll)NEXP*D3];
// fp16 weight copies
__device__ __half g_wspqkv[(ll)NEXP*D3*Dd];
__device__ __half g_wspo  [(ll)NEXP*Dd*Dd];
__device__ __half g_wtpqkv[(ll)NEXP*D3*Dd];   // packed q/k/v
__device__ __half g_wtpo  [(ll)NEXP*Dd*Dd];
__device__ __half g_wcqkv [(ll)3*Dd*Dd];
__device__ __half g_wco   [(ll)Dd*Dd];
__device__ __half g_wm1   [(ll)D4*Dd];
__device__ __half g_wm2   [(ll)Dd*D4];

__device__ __forceinline__ float gelu_exact(float v) {
    return 0.5f * v * (1.0f + erff(v * 0.70710678118654752f));
}
__device__ __forceinline__ uint32_t smem_u32(const void* p) {
    return (uint32_t)__cvta_generic_to_shared(p);
}

#define CP_ASYNC_16(dst_u32, src_ptr) \
    asm volatile("cp.async.cg.shared.global [%0], [%1], 16;\n" :: "r"(dst_u32), "l"(src_ptr))
#define CP_COMMIT() asm volatile("cp.async.commit_group;\n")
#define CP_WAIT(N)  asm volatile("cp.async.wait_group %0;\n" :: "n"(N))

__device__ __forceinline__ void ldsm_x4(uint32_t* r, uint32_t addr) {
    asm volatile("ldmatrix.sync.aligned.m8n8.x4.shared.b16 {%0,%1,%2,%3}, [%4];"
        : "=r"(r[0]), "=r"(r[1]), "=r"(r[2]), "=r"(r[3]) : "r"(addr));
}
__device__ __forceinline__ void ldsm_x4_t(uint32_t* r, uint32_t addr) {
    asm volatile("ldmatrix.sync.aligned.m8n8.x4.trans.shared.b16 {%0,%1,%2,%3}, [%4];"
        : "=r"(r[0]), "=r"(r[1]), "=r"(r[2]), "=r"(r[3]) : "r"(addr));
}
__device__ __forceinline__ void mma_fp16(float* c, const uint32_t* a, const uint32_t* b) {
    asm volatile(
        "mma.sync.aligned.m16n8k16.row.col.f32.f16.f16.f32 "
        "{%0,%1,%2,%3}, {%4,%5,%6,%7}, {%8,%9}, {%0,%1,%2,%3};"
        : "+f"(c[0]), "+f"(c[1]), "+f"(c[2]), "+f"(c[3])
        : "r"(a[0]), "r"(a[1]), "r"(a[2]), "r"(a[3]),
          "r"(b[0]), "r"(b[1]));
}
__device__ __forceinline__ uint32_t packh2(float a, float b) {
    __half2 h = __floats2half2_rn(a, b);
    return *(uint32_t*)&h;
}

// ---------------------------------------------------------------------------
// Mega weight convert (16 elems / thread) + temporal qkv packing
// ---------------------------------------------------------------------------
#define SEG_SPQKV ((ll)NEXP*D3*Dd)
#define SEG_DD    ((ll)NEXP*Dd*Dd)
#define SEG_CQKV  ((ll)3*Dd*Dd)
#define SEG_CO    ((ll)Dd*Dd)
#define SEG_M     ((ll)D4*Dd)
#define CONV_TOTAL (SEG_SPQKV + SEG_DD + 3*SEG_DD + SEG_DD + SEG_CQKV + SEG_CO + 2*SEG_M)

__device__ __forceinline__ void cvt16(__half* d, const float* s) {
    float4 v0 = *(const float4*)(s);
    float4 v1 = *(const float4*)(s + 4);
    float4 v2 = *(const float4*)(s + 8);
    float4 v3 = *(const float4*)(s + 12);
    *(__half2*)(d)      = __floats2half2_rn(v0.x, v0.y);
    *(__half2*)(d + 2)  = __floats2half2_rn(v0.z, v0.w);
    *(__half2*)(d + 4)  = __floats2half2_rn(v1.x, v1.y);
    *(__half2*)(d + 6)  = __floats2half2_rn(v1.z, v1.w);
    *(__half2*)(d + 8)  = __floats2half2_rn(v2.x, v2.y);
    *(__half2*)(d + 10) = __floats2half2_rn(v2.z, v2.w);
    *(__half2*)(d + 12) = __floats2half2_rn(v3.x, v3.y);
    *(__half2*)(d + 14) = __floats2half2_rn(v3.z, v3.w);
}

__global__ __launch_bounds__(256) void convert_all_kernel(
    const float* __restrict__ spqkv, const float* __restrict__ spo,
    const float* __restrict__ tq, const float* __restrict__ tk,
    const float* __restrict__ tv, const float* __restrict__ to,
    const float* __restrict__ cqkv, const float* __restrict__ cwo,
    const float* __restrict__ m1, const float* __restrict__ m2)
{
    ll i = ((ll)blockIdx.x * 256 + threadIdx.x) * 16;
    if (i >= CONV_TOTAL) return;
    ll o = i;
    if (o < SEG_SPQKV) { cvt16(g_wspqkv + o, spqkv + o); return; }
    o -= SEG_SPQKV;
    if (o < SEG_DD)    { cvt16(g_wspo + o, spo + o); return; }
    o -= SEG_DD;
    if (o < SEG_DD) {
        ll e = o / SEG_CO, rem = o - e * SEG_CO;
        cvt16(g_wtpqkv + e * ((ll)D3*Dd) + rem, tq + o); return;
    }
    o -= SEG_DD;
    if (o < SEG_DD) {
        ll e = o / SEG_CO, rem = o - e * SEG_CO;
        cvt16(g_wtpqkv + e * ((ll)D3*Dd) + (ll)Dd*Dd + rem, tk + o); return;
    }
    o -= SEG_DD;
    if (o < SEG_DD) {
        ll e = o / SEG_CO, rem = o - e * SEG_CO;
        cvt16(g_wtpqkv + e * ((ll)D3*Dd) + (ll)2*Dd*Dd + rem, tv + o); return;
    }
    o -= SEG_DD;
    if (o < SEG_DD)   { cvt16(g_wtpo + o, to + o); return; }
    o -= SEG_DD;
    if (o < SEG_CQKV) { cvt16(g_wcqkv + o, cqkv + o); return; }
    o -= SEG_CQKV;
    if (o < SEG_CO)   { cvt16(g_wco + o, cwo + o); return; }
    o -= SEG_CO;
    if (o < SEG_M)    { cvt16(g_wm1 + o, m1 + o); return; }
    o -= SEG_M;
    cvt16(g_wm2 + o, m2 + o);
}

__global__ void pack_btp_kernel(const float* __restrict__ bq,
                                const float* __restrict__ bk,
                                const float* __restrict__ bv)
{
    int i = blockIdx.x * 256 + threadIdx.x;
    if (i >= NEXP * D3) return;
    int e = i / D3, j = i - e * D3;
    float v = (j < Dd) ? bq[e*Dd + j] : (j < 2*Dd) ? bk[e*Dd + j - Dd] : bv[e*Dd + j - 2*Dd];
    g_btp[i] = v;
}

// ---------------------------------------------------------------------------
// Router
// ---------------------------------------------------------------------------
__global__ void router_kernel(const float* __restrict__ x,
                              const float* __restrict__ w1, const float* __restrict__ b1,
                              const float* __restrict__ w2, const float* __restrict__ b2,
                              int* __restrict__ idx_s, int* __restrict__ idx_t)
{
    __shared__ float xm[Dd];
    __shared__ float hbuf[RH];
    __shared__ float lg[8];
    int b = blockIdx.x;
    int d = threadIdx.x;
    const float* xb = x + (ll)b * Tt * Dd;
    float s = 0.f;
    for (int t = 0; t < Tt; t++) s += xb[(ll)t * Dd + d];
    xm[d] = s * (1.0f / Tt);
    __syncthreads();
    if (d < RH) {
        float a = b1[d];
        const float* wr = w1 + (ll)d * Dd;
        for (int k = 0; k < Dd; k++) a += xm[k] * wr[k];
        hbuf[d] = gelu_exact(a);
    }
    __syncthreads();
    if (d < 8) {
        float a = b2[d];
        const float* wr = w2 + d * RH;
        for (int k = 0; k < RH; k++) a += hbuf[k] * wr[k];
        lg[d] = a;
    }
    __syncthreads();
    if (d == 0) {
        int is = 0; for (int i = 1; i < NEXP; i++) if (lg[i] > lg[is]) is = i;
        int it = 0; for (int i = 1; i < NEXP; i++) if (lg[NEXP+i] > lg[NEXP+it]) it = i;
        idx_s[b] = is;
        idx_t[b] = it;
    }
}

// ---------------------------------------------------------------------------
// Fused dual-output LayerNorm (validated R14)
// ---------------------------------------------------------------------------
__global__ __launch_bounds__(256) void ln_dual_kernel(const float* __restrict__ x,
    const float* __restrict__ g0, const float* __restrict__ b0,
    __half* __restrict__ yh0,
    const float* __restrict__ g1, const float* __restrict__ b1,
    __half* __restrict__ yh1, float* __restrict__ yf1)
{
    __shared__ float2 sw[8];
    ll row = blockIdx.x;
    int t = threadIdx.x, lane = t & 31, wid = t >> 5;
    const float* xr = x + row * Dd;
    float a0 = xr[t], a1 = xr[t+256], a2 = xr[t+512];
    float s = a0 + a1 + a2;
    float s2 = a0*a0 + a1*a1 + a2*a2;
    #pragma unroll
    for (int o = 16; o; o >>= 1) {
        s  += __shfl_xor_sync(0xFFFFFFFFu, s, o);
        s2 += __shfl_xor_sync(0xFFFFFFFFu, s2, o);
    }
    if (lane == 0) sw[wid] = make_float2(s, s2);
    __syncthreads();
    if (t < 8) {
        float2 v = sw[t];
        float u = v.x, u2 = v.y;
        #pragma unroll
        for (int o = 4; o; o >>= 1) {
            u  += __shfl_xor_sync(0xFFu, u, o);
            u2 += __shfl_xor_sync(0xFFu, u2, o);
        }
        if (t == 0) sw[0] = make_float2(u, u2);
    }
    __syncthreads();
    float2 tot = sw[0];
    float mean = tot.x * (1.0f / Dd);
    float var = tot.y * (1.0f / Dd) - mean * mean;
    float inv = rsqrtf(var + LN_EPS);
    float n0 = (a0 - mean) * inv;
    float n1 = (a1 - mean) * inv;
    float n2 = (a2 - mean) * inv;
    {
        float v0 = n0 * g0[t]     + b0[t];
        float v1 = n1 * g0[t+256] + b0[t+256];
        float v2 = n2 * g0[t+512] + b0[t+512];
        __half* yr = yh0 + row * Dd;
        yr[t]     = __float2half_rn(v0);
        yr[t+256] = __float2half_rn(v1);
        yr[t+512] = __float2half_rn(v2);
    }
    {
        float v0 = n0 * g1[t]     + b1[t];
        float v1 = n1 * g1[t+256] + b1[t+256];
        float v2 = n2 * g1[t+512] + b1[t+512];
        __half* yr = yh1 + row * Dd;
        yr[t]     = __float2half_rn(v0);
        yr[t+256] = __float2half_rn(v1);
        yr[t+512] = __float2half_rn(v2);
        float* yfr = yf1 + row * Dd;
        yfr[t] = v0; yfr[t+256] = v1; yfr[t+512] = v2;
    }
}

// Single-set LN (MLP)
__global__ __launch_bounds__(256) void ln_kernel(const float* __restrict__ x,
    const float* __restrict__ g, const float* __restrict__ bb,
    __half* __restrict__ yh)
{
    __shared__ float2 sw[8];
    ll row = blockIdx.x;
    int t = threadIdx.x, lane = t & 31, wid = t >> 5;
    const float* xr = x + row * Dd;
    float a0 = xr[t], a1 = xr[t+256], a2 = xr[t+512];
    float s = a0 + a1 + a2;
    float s2 = a0*a0 + a1*a1 + a2*a2;
    #pragma unroll
    for (int o = 16; o; o >>= 1) {
        s  += __shfl_xor_sync(0xFFFFFFFFu, s, o);
        s2 += __shfl_xor_sync(0xFFFFFFFFu, s2, o);
    }
    if (lane == 0) sw[wid] = make_float2(s, s2);
    __syncthreads();
    if (t < 8) {
        float2 v = sw[t];
        float u = v.x, u2 = v.y;
        #pragma unroll
        for (int o = 4; o; o >>= 1) {
            u  += __shfl_xor_sync(0xFFu, u, o);
            u2 += __shfl_xor_sync(0xFFu, u2, o);
        }
        if (t == 0) sw[0] = make_float2(u, u2);
    }
    __syncthreads();
    float2 tot = sw[0];
    float mean = tot.x * (1.0f / Dd);
    float var = tot.y * (1.0f / Dd) - mean * mean;
    float inv = rsqrtf(var + LN_EPS);
    __half* yr = yh + row * Dd;
    yr[t]     = __float2half_rn((a0 - mean) * inv * g[t]     + bb[t]);
    yr[t+256] = __float2half_rn((a1 - mean) * inv * g[t+256] + bb[t+256]);
    yr[t+512] = __float2half_rn((a2 - mean) * inv * g[t+512] + bb[t+512]);
}

// ---------------------------------------------------------------------------
// Flash attention (dual-set): Q is PRE-SCALED by 1/sqrt(HD) at the producer
// GEMM, so no per-tile scaling here. Otherwise validated R8 structure.
// ---------------------------------------------------------------------------
#define FL_KLD  104
#define FL_TILE (128 * FL_KLD)
#define FL_TILEB (FL_TILE * 2)
#define FL_SMEM (3 * FL_TILEB)         // 79872

__device__ __forceinline__ void fl_load_tile(const __half* gbase, int row0,
                                             __half* dstsm, int cr, int cc)
{
    #pragma unroll
    for (int rp = 0; rp < 2; rp++) {
        int r = rp * 64 + cr;
        const __half* src = gbase + (ll)(row0 + r) * D3 + cc;
        uint32_t dst = smem_u32(dstsm) + (uint32_t)((r * FL_KLD + cc) * 2);
        CP_ASYNC_16(dst,      src);
        CP_ASYNC_16(dst + 16, src + 8);
        CP_ASYNC_16(dst + 32, src + 16);
    }
}

__global__ __launch_bounds__(256, 1) void flash_kernel(
    const __half* __restrict__ QKVa, __half* __restrict__ Oa, int causalA,
    const __half* __restrict__ QKVb, __half* __restrict__ Ob, int causalB)
{
    extern __shared__ __half fsm[];
    __half* Ksm = fsm;
    __half* Vsm = fsm + FL_TILE;

    int z = blockIdx.z;
    const __half* QKV; __half* O; int causal; int b;
    if (z < Bz) { QKV = QKVa; O = Oa; causal = causalA; b = z; }
    else        { QKV = QKVb; O = Ob; causal = causalB; b = z - Bz; }

    int qt = blockIdx.x, h = blockIdx.y;
    int q0 = qt * 128;
    int tid = threadIdx.x, lane = tid & 31, w = tid >> 5;
    int g = lane >> 2, t4 = lane & 3;

    const __half* Qg = QKV + (ll)b * (Tt * D3) + (ll)q0 * D3 + h * HD;
    const __half* Kg = QKV + (ll)b * (Tt * D3) + Dd + h * HD;
    const __half* Vg = Kg + Dd;

    int cr = tid >> 2;
    int cc = (tid & 3) * 24;

    #pragma unroll
    for (int rp = 0; rp < 2; rp++) {
        int r = rp * 64 + cr;
        const __half* src = Qg + (ll)r * D3 + cc;
        uint32_t dst = smem_u32(Ksm) + (uint32_t)((r * FL_KLD + cc) * 2);
        CP_ASYNC_16(dst,      src);
        CP_ASYNC_16(dst + 16, src + 8);
        CP_ASYNC_16(dst + 32, src + 16);
    }
    CP_COMMIT(); CP_WAIT(0);
    __syncthreads();

    uint32_t qfr[6][4];
    {
        uint32_t aBase = smem_u32(Ksm) +
            (uint32_t)(((((lane & 15) + w * 16)) * FL_KLD + ((lane >> 4) << 3)) * 2);
        #pragma unroll
        for (int ks = 0; ks < 6; ks++) ldsm_x4(qfr[ks], aBase + ks * 32);
    }
    __syncthreads();

    int nk = causal ? (q0 / 128 + 1) : (Tt / 128);

    fl_load_tile(Kg, 0, Ksm, cr, cc);
    fl_load_tile(Vg, 0, Vsm, cr, cc);
    CP_COMMIT();

    float mrow[2] = {-1e30f, -1e30f};
    float lrow[2] = {0.f, 0.f};
    float oacc[12][4];
    #pragma unroll
    for (int j = 0; j < 12; j++)
        #pragma unroll
        for (int q = 0; q < 4; q++) oacc[j][q] = 0.f;

    uint32_t kBase = smem_u32(Ksm) +
        (uint32_t)(((((lane & 7) + ((lane >> 4) << 3))) * FL_KLD + (((lane >> 3) & 1) << 3)) * 2);
    uint32_t vBase = smem_u32(Vsm) +
        (uint32_t)(((((lane & 7) + (((lane >> 3) & 1) << 3))) * FL_KLD + ((lane >> 4) << 3)) * 2);

    for (int kt = 0; kt < nk; kt++) {
        CP_WAIT(0);
        __syncthreads();
        int cur = kt & 1;

        float s[16][4];
        #pragma unroll
        for (int j = 0; j < 16; j++)
            #pragma unroll
            for (int q = 0; q < 4; q++) s[j][q] = 0.f;

        #pragma unroll
        for (int ks = 0; ks < 6; ks++) {
            #pragma unroll
            for (int jp = 0; jp < 8; jp++) {
                uint32_t rb[4];
                ldsm_x4(rb, kBase + jp * (16 * FL_KLD * 2) + ks * 32);
                mma_fp16(s[2*jp],   qfr[ks], rb);
                mma_fp16(s[2*jp+1], qfr[ks], rb + 2);
            }
        }

        bool domask = causal && (kt * 128 + 127 > q0);
        if (domask) {
            int rbase = q0 + w * 16 + g;
            #pragma unroll
            for (int j = 0; j < 16; j++) {
                int key0 = kt * 128 + j * 8 + 2 * t4;
                #pragma unroll
                for (int q = 0; q < 4; q++) {
                    int key = key0 + (q & 1);
                    int row = rbase + ((q >> 1) << 3);
                    if (key > row) s[j][q] = -1e30f;
                }
            }
        }

        uint32_t p[8][4];
        #pragma unroll
        for (int hf = 0; hf < 2; hf++) {
            float mx = -1e30f;
            #pragma unroll
            for (int j = 0; j < 16; j++)
                mx = fmaxf(mx, fmaxf(s[j][hf*2], s[j][hf*2+1]));
            mx = fmaxf(mx, __shfl_xor_sync(0xFFFFFFFFu, mx, 1));
            mx = fmaxf(mx, __shfl_xor_sync(0xFFFFFFFFu, mx, 2));
            float mnew = fmaxf(mrow[hf], mx);
            float corr = expf(mrow[hf] - mnew);
            mrow[hf] = mnew;
            float rsum = 0.f;
            #pragma unroll
            for (int j = 0; j < 16; j++) {
                float e0 = expf(s[j][hf*2]   - mnew);
                float e1 = expf(s[j][hf*2+1] - mnew);
                s[j][hf*2] = e0; s[j][hf*2+1] = e1;
                rsum += e0 + e1;
            }
            rsum += __shfl_xor_sync(0xFFFFFFFFu, rsum, 1);
            rsum += __shfl_xor_sync(0xFFFFFFFFu, rsum, 2);
            lrow[hf] = lrow[hf] * corr + rsum;
            #pragma unroll
            for (int j = 0; j < 12; j++) {
                oacc[j][hf*2]   *= corr;
                oacc[j][hf*2+1] *= corr;
            }
        }
        #pragma unroll
        for (int ksv = 0; ksv < 8; ksv++) {
            p[ksv][0] = packh2(s[2*ksv][0],   s[2*ksv][1]);
            p[ksv][1] = packh2(s[2*ksv][2],   s[2*ksv][3]);
            p[ksv][2] = packh2(s[2*ksv+1][0], s[2*ksv+1][1]);
            p[ksv][3] = packh2(s[2*ksv+1][2], s[2*ksv+1][3]);
        }

        __syncthreads();
        if (kt + 1 < nk) {
            fl_load_tile(Kg, (kt+1) * 128, Ksm, cr, cc);
            fl_load_tile(Vg, (kt+1) * 128, Vsm + (1 - cur) * FL_TILE, cr, cc);
            CP_COMMIT();
        }

        uint32_t vb = vBase + cur * FL_TILEB;
        #pragma unroll
        for (int ksv = 0; ksv < 8; ksv++) {
            #pragma unroll
            for (int jp = 0; jp < 6; jp++) {
                uint32_t rb[4];
                ldsm_x4_t(rb, vb + ksv * (16 * FL_KLD * 2) + jp * 32);
                mma_fp16(oacc[2*jp],   p[ksv], rb);
                mma_fp16(oacc[2*jp+1], p[ksv], rb + 2);
            }
        }
    }

    #pragma unroll
    for (int hf = 0; hf < 2; hf++) {
        float inv = 1.f / lrow[hf];
        int r = q0 + w * 16 + g + hf * 8;
        __half* orow = O + (ll)b * (Tt * Dd) + (ll)r * Dd + h * HD;
        #pragma unroll
        for (int j = 0; j < 12; j++) {
            *(__half2*)(orow + j * 8 + 2 * t4) =
                __floats2half2_rn(oacc[j][hf*2] * inv, oacc[j][hf*2+1] * inv);
        }
    }
}

// ---------------------------------------------------------------------------
// FP16 NT GEMM engine (exact R8): 128 threads, 4 warps (2m x 2n),
// warp tile 64x64, block 128x128, BK=32, 4-stage cp.async, 2 CTA/SM.
// qCols: output columns with n0 < qCols are scaled by SCALE_V (after bias).
// ---------------------------------------------------------------------------
#define ALD   40
#define ASTG  (128 * ALD)
#define ASTGB (ASTG * 2)
#define GEMM_SMEM (2 * STAGES * ASTGB)   // 81920

struct GemmP {
    const __half* A;     // [rows, Kd], batch stride Tt*Kd
    const __half* W;     // [N, Kd] (+ expert stride)
    ll esW;
    const int* eidx;
    const float* bias;   // fp32 [N] (+ expert stride esBias)
    int esBias;
    const float* res;    // fp32 [rows, Dd], batch stride Tt*Dd
    void* C;             // ldc, batch stride Tt*ldc
    int ldc;
    int cHalf;
    int Kd;
    int act;
    int qCols;           // columns < qCols get scaled by SCALE_V
};

__device__ __forceinline__ void gemm_body(const GemmP p, int b, int m0, int n0)
{
    extern __shared__ __half hsm[];
    __half* Asm = hsm;
    __half* Wsm = hsm + STAGES * ASTG;

    const __half* A = p.A + (ll)b * Tt * p.Kd;
    ll woff = 0;
    const float* biasp = p.bias;
    if (p.eidx) {
        int e = p.eidx[b];
        woff = (ll)e * p.esW;
        if (biasp) biasp += (ll)e * p.esBias;
    }
    const __half* W = p.W + woff;
    const float* res = p.res ? (p.res + (ll)b * (Tt * Dd)) : nullptr;

    int tid = threadIdx.x, lane = tid & 31, warp = tid >> 5;
    int wm = warp & 1, wn = warp >> 1;
    int wmb = wm * 64, wnb = wn * 64;
    int g = lane >> 2, t4 = lane & 3;

    int r0 = tid >> 2, c0 = (tid & 3) * 8;
    const __half* Ap = A + (ll)(m0 + r0) * p.Kd + c0;
    const __half* Wp = W + (ll)(n0 + r0) * p.Kd + c0;
    uint32_t dA = smem_u32(Asm) + (uint32_t)((r0 * ALD + c0) * 2);
    uint32_t dW = smem_u32(Wsm) + (uint32_t)((r0 * ALD + c0) * 2);
    ll rowStep = (ll)32 * p.Kd;

    float acc[4][8][4];
    #pragma unroll
    for (int i = 0; i < 4; i++)
        #pragma unroll
        for (int j = 0; j < 8; j++)
            #pragma unroll
            for (int q = 0; q < 4; q++) acc[i][j][q] = 0.f;

    uint32_t aBase = smem_u32(Asm) +
        (uint32_t)((((lane & 15) + wmb) * ALD + ((lane >> 4) << 3)) * 2);
    uint32_t bBase = smem_u32(Wsm) +
        (uint32_t)((((lane & 7) + ((lane >> 4) << 3) + wnb) * ALD + (((lane >> 3) & 1) << 3)) * 2);

    int kTiles = p.Kd >> 5;

    #pragma unroll
    for (int s = 0; s < STAGES - 1; s++) {
        if (s < kTiles) {
            const __half* a = Ap + s * 32;
            const __half* w = Wp + s * 32;
            #pragma unroll
            for (int rp = 0; rp < 4; rp++) {
                CP_ASYNC_16(dA + s * ASTGB + rp * (32 * ALD * 2), a + rp * rowStep);
                CP_ASYNC_16(dW + s * ASTGB + rp * (32 * ALD * 2), w + rp * rowStep);
            }
        }
        CP_COMMIT();
    }

    for (int kt = 0; kt < kTiles; kt++) {
        CP_WAIT(STAGES - 2);
        __syncthreads();

        int pf = kt + STAGES - 1;
        if (pf < kTiles) {
            int ps = pf & (STAGES - 1);
            const __half* a = Ap + pf * 32;
            const __half* w = Wp + pf * 32;
            #pragma unroll
            for (int rp = 0; rp < 4; rp++) {
                CP_ASYNC_16(dA + ps * ASTGB + rp * (32 * ALD * 2), a + rp * rowStep);
                CP_ASYNC_16(dW + ps * ASTGB + rp * (32 * ALD * 2), w + rp * rowStep);
            }
        }
        CP_COMMIT();

        uint32_t sa = aBase + (kt & (STAGES - 1)) * ASTGB;
        uint32_t sb = bBase + (kt & (STAGES - 1)) * ASTGB;
        #pragma unroll
        for (int ks = 0; ks < 2; ks++) {
            uint32_t afr[4][4], bfr[8][2];
            #pragma unroll
            for (int im = 0; im < 4; im++)
                ldsm_x4(afr[im], sa + im * (16 * ALD * 2) + ks * 32);
            #pragma unroll
            for (int jp = 0; jp < 4; jp++) {
                uint32_t rb[4];
                ldsm_x4(rb, sb + jp * (16 * ALD * 2) + ks * 32);
                bfr[2*jp][0]   = rb[0]; bfr[2*jp][1]   = rb[1];
                bfr[2*jp+1][0] = rb[2]; bfr[2*jp+1][1] = rb[3];
            }
            #pragma unroll
            for (int im = 0; im < 4; im++)
                #pragma unroll
                for (int jn = 0; jn < 8; jn++)
                    mma_fp16(acc[im][jn], afr[im], bfr[jn]);
        }
    }

    float alpha = (n0 < p.qCols) ? SCALE_V : 1.0f;

    __half* Ch = (__half*)p.C;
    float*  Cf = (float*)p.C;
    ll cb = (ll)b * Tt * p.ldc;
    #pragma unroll
    for (int im = 0; im < 4; im++) {
        int rr0 = m0 + wmb + im * 16 + g;
        #pragma unroll
        for (int jn = 0; jn < 8; jn++) {
            int c = n0 + wnb + jn * 8 + 2 * t4;
            float bv0 = biasp ? biasp[c]     : 0.f;
            float bv1 = biasp ? biasp[c + 1] : 0.f;
            #pragma unroll
            for (int hf = 0; hf < 2; hf++) {
                int r = rr0 + hf * 8;
                float v0 = (acc[im][jn][hf*2+0] + bv0) * alpha;
                float v1 = (acc[im][jn][hf*2+1] + bv1) * alpha;
                if (p.act) { v0 = gelu_exact(v0); v1 = gelu_exact(v1); }
                if (res) {
                    const float* rp2 = res + (ll)r * Dd + c;
                    v0 += rp2[0]; v1 += rp2[1];
                }
                if (p.cHalf)
                    *(__half2*)(Ch + cb + (ll)r * p.ldc + c) = __floats2half2_rn(v0, v1);
                else
                    *(float2*)(Cf + cb + (ll)r * p.ldc + c) = make_float2(v0, v1);
            }
        }
    }
}

__global__ __launch_bounds__(128, 2) void hgemm_one(GemmP p) {
    gemm_body(p, blockIdx.z, blockIdx.y * 128, blockIdx.x * 128);
}
__global__ __launch_bounds__(128, 2) void hgemm_dualz(GemmP p0, GemmP p1) {
    int z = blockIdx.z;
    if (z < Bz) gemm_body(p0, z, blockIdx.y * 128, blockIdx.x * 128);
    else        gemm_body(p1, z - Bz, blockIdx.y * 128, blockIdx.x * 128);
}
__global__ __launch_bounds__(128, 2) void hgemm_dualx(GemmP p0, GemmP p1, int xsplit) {
    int xb = blockIdx.x;
    if (xb < xsplit) gemm_body(p0, blockIdx.z, blockIdx.y * 128, xb * 128);
    else             gemm_body(p1, blockIdx.z, blockIdx.y * 128, (xb - xsplit) * 128);
}

// ---------------------------------------------------------------------------
// Orchestration
// ---------------------------------------------------------------------------
extern "C" void kernel_launch(void* const* d_in, const int* in_sizes, int n_in,
                              void* d_out, int out_size)
{
    const float* x        = (const float*)d_in[0];
    const float* rw1      = (const float*)d_in[1];
    const float* rb1      = (const float*)d_in[2];
    const float* rw2      = (const float*)d_in[3];
    const float* rb2      = (const float*)d_in[4];
    const float* nsg      = (const float*)d_in[5];
    const float* nsb      = (const float*)d_in[6];
    const float* ntg      = (const float*)d_in[7];
    const float* ntb      = (const float*)d_in[8];
    const float* nmg      = (const float*)d_in[9];
    const float* nmb      = (const float*)d_in[10];
    const float* sp_wqkv  = (const float*)d_in[11];
    const float* sp_bqkv  = (const float*)d_in[12];
    const float* sp_wo    = (const float*)d_in[13];
    const float* sp_bo    = (const float*)d_in[14];
    const float* tp_wq    = (const float*)d_in[15];
    const float* tp_bq    = (const float*)d_in[16];
    const float* tp_wk    = (const float*)d_in[17];
    const float* tp_bk    = (const float*)d_in[18];
    const float* tp_wv    = (const float*)d_in[19];
    const float* tp_bv    = (const float*)d_in[20];
    const float* tp_wo    = (const float*)d_in[21];
    const float* tp_bo    = (const float*)d_in[22];
    const float* c_wqkv   = (const float*)d_in[23];
    const float* c_bqkv   = (const float*)d_in[24];
    const float* c_wo     = (const float*)d_in[25];
    const float* c_bo     = (const float*)d_in[26];
    const float* mlp_w1   = (const float*)d_in[27];
    const float* mlp_b1   = (const float*)d_in[28];
    const float* mlp_w2   = (const float*)d_in[29];
    const float* mlp_b2   = (const float*)d_in[30];
    float* out = (float*)d_out;

    static int attr_done = 0;
    if (!attr_done) {
        cudaFuncSetAttribute(hgemm_one,   cudaFuncAttributeMaxDynamicSharedMemorySize, GEMM_SMEM);
        cudaFuncSetAttribute(hgemm_dualz, cudaFuncAttributeMaxDynamicSharedMemorySize, GEMM_SMEM);
        cudaFuncSetAttribute(hgemm_dualx, cudaFuncAttributeMaxDynamicSharedMemorySize, GEMM_SMEM);
        cudaFuncSetAttribute(flash_kernel, cudaFuncAttributeMaxDynamicSharedMemorySize, FL_SMEM);
        attr_done = 1;
    }

    float *xtf, *x1, *btp;
    __half *qkv, *qkv2, *xnh, *xth, *attno, *attno2, *spout, *tpout, *hid;
    __half *wspqkv, *wspo, *wtpqkv, *wtpo, *wcqkv, *wco, *wm1, *wm2;
    int* idx;
    cudaGetSymbolAddress((void**)&qkv,    g_qkvh);
    cudaGetSymbolAddress((void**)&qkv2,   g_qkv2h);
    cudaGetSymbolAddress((void**)&xnh,    g_xnh);
    cudaGetSymbolAddress((void**)&xth,    g_xth);
    cudaGetSymbolAddress((void**)&xtf,    g_xtf);
    cudaGetSymbolAddress((void**)&attno,  g_attno);
    cudaGetSymbolAddress((void**)&attno2, g_attno2);
    cudaGetSymbolAddress((void**)&spout,  g_spout);
    cudaGetSymbolAddress((void**)&tpout,  g_tpout);
    cudaGetSymbolAddress((void**)&x1,     g_x1);
    cudaGetSymbolAddress((void**)&hid,    g_hid);
    cudaGetSymbolAddress((void**)&idx,    g_idx);
    cudaGetSymbolAddress((void**)&btp,    g_btp);
    cudaGetSymbolAddress((void**)&wspqkv, g_wspqkv);
    cudaGetSymbolAddress((void**)&wspo,   g_wspo);
    cudaGetSymbolAddress((void**)&wtpqkv, g_wtpqkv);
    cudaGetSymbolAddress((void**)&wtpo,   g_wtpo);
    cudaGetSymbolAddress((void**)&wcqkv,  g_wcqkv);
    cudaGetSymbolAddress((void**)&wco,    g_wco);
    cudaGetSymbolAddress((void**)&wm1,    g_wm1);
    cudaGetSymbolAddress((void**)&wm2,    g_wm2);

    // ---- weight conversion + bias packing + router ----
    {
        int blocks = (int)((CONV_TOTAL / 16 + 255) / 256);
        convert_all_kernel<<<blocks, 256>>>(sp_wqkv, sp_wo, tp_wq, tp_wk, tp_wv,
                                            tp_wo, c_wqkv, c_wo, mlp_w1, mlp_w2);
        pack_btp_kernel<<<(NEXP*D3 + 255)/256, 256>>>(tp_bq, tp_bk, tp_bv);
    }
    router_kernel<<<Bz, Dd>>>(x, rw1, rb1, rw2, rb2, idx, idx + 8);

    // ---- LN (spatial + temporal fused into ONE pass over x) ----
    ln_dual_kernel<<<4096, 256>>>(x, nsg, nsb, xnh, ntg, ntb, xth, xtf);

    // ---- QKV GEMMs (spatial + temporal fused; Q cols pre-scaled) ----
    {
        GemmP p0 = { xnh, wspqkv, (ll)D3 * Dd, idx,     sp_bqkv, D3, nullptr, qkv,  D3, 1, Dd, 0, Dd };
        GemmP p1 = { xth, wtpqkv, (ll)D3 * Dd, idx + 8, btp,     D3, nullptr, qkv2, D3, 1, Dd, 0, Dd };
        hgemm_dualz<<<dim3(D3/128, Tt/128, 2*Bz), 128, GEMM_SMEM>>>(p0, p1);
    }

    // ---- flash (spatial non-causal + temporal causal fused) ----
    flash_kernel<<<dim3(Tt/128, Hh, 2*Bz), 256, FL_SMEM>>>(qkv, attno, 0, qkv2, attno2, 1);

    // ---- output projections (spatial + temporal fused) ----
    {
        GemmP p0 = { attno,  wspo, (ll)Dd * Dd, idx,     sp_bo, Dd, nullptr, spout, Dd, 1, Dd, 0, 0 };
        GemmP p1 = { attno2, wtpo, (ll)Dd * Dd, idx + 8, tp_bo, Dd, xtf,     tpout, Dd, 1, Dd, 0, 0 };
        hgemm_dualz<<<dim3(Dd/128, Tt/128, 2*Bz), 128, GEMM_SMEM>>>(p0, p1);
    }

    // ---- cross q (from spout; pre-scaled) + cross kv (from tpout) ----
    {
        GemmP p0 = { spout, wcqkv,                0, nullptr, c_bqkv,      0, nullptr, qkv,      D3, 1, Dd, 0, Dd };
        GemmP p1 = { tpout, wcqkv + (ll)Dd * Dd,  0, nullptr, c_bqkv + Dd, 0, nullptr, qkv + Dd, D3, 1, Dd, 0, 0 };
        hgemm_dualx<<<dim3(18, Tt/128, Bz), 128, GEMM_SMEM>>>(p0, p1, 6);
    }

    // ---- cross flash ----
    flash_kernel<<<dim3(Tt/128, Hh, Bz), 256, FL_SMEM>>>(qkv, attno, 0, qkv, attno, 0);

    // ---- cross out: x1 = x + attno @ wco^T + c_bo (fp32) ----
    {
        GemmP p = { attno, wco, 0, nullptr, c_bo, 0, x, x1, Dd, 0, Dd, 0, 0 };
        hgemm_one<<<dim3(Dd/128, Tt/128, Bz), 128, GEMM_SMEM>>>(p);
    }

    // ---- MLP ----
    ln_kernel<<<4096, 256>>>(x1, nmg, nmb, xnh);

    {
        GemmP p = { xnh, wm1, 0, nullptr, mlp_b1, 0, nullptr, hid, D4, 1, Dd, 1, 0 };
        hgemm_one<<<dim3(D4/128, (Bz*Tt)/128, 1), 128, GEMM_SMEM>>>(p);
    }
    {
        GemmP p = { hid, wm2, 0, nullptr, mlp_b2, 0, x1, out, Dd, 0, D4, 0, 0 };
        hgemm_one<<<dim3(Dd/128, (Bz*Tt)/128, 1), 128, GEMM_SMEM>>>(p);
    }
}

// round 17
// speedup vs baseline: 1.0771x; 1.0048x over previous
#include <cuda_runtime.h>
#include <cuda_fp16.h>
#include <math.h>
#include <stdint.h>

typedef long long ll;

// ---------------------------------------------------------------------------
// Problem constants
// ---------------------------------------------------------------------------
#define Bz   8
#define Tt   512
#define Dd   768
#define Hh   8
#define HD   96
#define NEXP 4
#define RH   128
#define D3   (3*Dd)     // 2304
#define D4   (4*Dd)     // 3072
#define SCALE_V (0.10206207261596575f)  // 1/sqrt(96)
#define LN_EPS 1e-5f
#define STAGES 4

// ---------------------------------------------------------------------------
// Scratch (static device arrays -- no allocation allowed)
// ---------------------------------------------------------------------------
__device__ __half g_qkvh  [(ll)Bz*Tt*D3];
__device__ __half g_qkv2h [(ll)Bz*Tt*D3];
__device__ __half g_xnh   [(ll)Bz*Tt*Dd];
__device__ __half g_xth   [(ll)Bz*Tt*Dd];
__device__ float  g_xtf   [(ll)Bz*Tt*Dd];
__device__ __half g_attno [(ll)Bz*Tt*Dd];
__device__ __half g_attno2[(ll)Bz*Tt*Dd];
__device__ __half g_spout [(ll)Bz*Tt*Dd];
__device__ __half g_tpout [(ll)Bz*Tt*Dd];
__device__ float  g_x1    [(ll)Bz*Tt*Dd];
__device__ __half g_hid   [(ll)Bz*Tt*D4];
__device__ int    g_idx   [16];
__device__ float  g_btp   [(ll)NEXP*D3];
// fp16 weight copies
__device__ __half g_wspqkv[(ll)NEXP*D3*Dd];
__device__ __half g_wspo  [(ll)NEXP*Dd*Dd];
__device__ __half g_wtpqkv[(ll)NEXP*D3*Dd];   // packed q/k/v
__device__ __half g_wtpo  [(ll)NEXP*Dd*Dd];
__device__ __half g_wcqkv [(ll)3*Dd*Dd];
__device__ __half g_wco   [(ll)Dd*Dd];
__device__ __half g_wm1   [(ll)D4*Dd];
__device__ __half g_wm2   [(ll)Dd*D4];

__device__ __forceinline__ float gelu_exact(float v) {
    return 0.5f * v * (1.0f + erff(v * 0.70710678118654752f));
}
__device__ __forceinline__ uint32_t smem_u32(const void* p) {
    return (uint32_t)__cvta_generic_to_shared(p);
}

#define CP_ASYNC_16(dst_u32, src_ptr) \
    asm volatile("cp.async.cg.shared.global [%0], [%1], 16;\n" :: "r"(dst_u32), "l"(src_ptr))
#define CP_COMMIT() asm volatile("cp.async.commit_group;\n")
#define CP_WAIT(N)  asm volatile("cp.async.wait_group %0;\n" :: "n"(N))

__device__ __forceinline__ void ldsm_x4(uint32_t* r, uint32_t addr) {
    asm volatile("ldmatrix.sync.aligned.m8n8.x4.shared.b16 {%0,%1,%2,%3}, [%4];"
        : "=r"(r[0]), "=r"(r[1]), "=r"(r[2]), "=r"(r[3]) : "r"(addr));
}
__device__ __forceinline__ void ldsm_x4_t(uint32_t* r, uint32_t addr) {
    asm volatile("ldmatrix.sync.aligned.m8n8.x4.trans.shared.b16 {%0,%1,%2,%3}, [%4];"
        : "=r"(r[0]), "=r"(r[1]), "=r"(r[2]), "=r"(r[3]) : "r"(addr));
}
__device__ __forceinline__ void mma_fp16(float* c, const uint32_t* a, const uint32_t* b) {
    asm volatile(
        "mma.sync.aligned.m16n8k16.row.col.f32.f16.f16.f32 "
        "{%0,%1,%2,%3}, {%4,%5,%6,%7}, {%8,%9}, {%0,%1,%2,%3};"
        : "+f"(c[0]), "+f"(c[1]), "+f"(c[2]), "+f"(c[3])
        : "r"(a[0]), "r"(a[1]), "r"(a[2]), "r"(a[3]),
          "r"(b[0]), "r"(b[1]));
}
__device__ __forceinline__ uint32_t packh2(float a, float b) {
    __half2 h = __floats2half2_rn(a, b);
    return *(uint32_t*)&h;
}

// ---------------------------------------------------------------------------
// Mega weight convert (16 elems / thread) + temporal qkv packing
// ---------------------------------------------------------------------------
#define SEG_SPQKV ((ll)NEXP*D3*Dd)
#define SEG_DD    ((ll)NEXP*Dd*Dd)
#define SEG_CQKV  ((ll)3*Dd*Dd)
#define SEG_CO    ((ll)Dd*Dd)
#define SEG_M     ((ll)D4*Dd)
#define CONV_TOTAL (SEG_SPQKV + SEG_DD + 3*SEG_DD + SEG_DD + SEG_CQKV + SEG_CO + 2*SEG_M)

__device__ __forceinline__ void cvt16(__half* d, const float* s) {
    float4 v0 = *(const float4*)(s);
    float4 v1 = *(const float4*)(s + 4);
    float4 v2 = *(const float4*)(s + 8);
    float4 v3 = *(const float4*)(s + 12);
    *(__half2*)(d)      = __floats2half2_rn(v0.x, v0.y);
    *(__half2*)(d + 2)  = __floats2half2_rn(v0.z, v0.w);
    *(__half2*)(d + 4)  = __floats2half2_rn(v1.x, v1.y);
    *(__half2*)(d + 6)  = __floats2half2_rn(v1.z, v1.w);
    *(__half2*)(d + 8)  = __floats2half2_rn(v2.x, v2.y);
    *(__half2*)(d + 10) = __floats2half2_rn(v2.z, v2.w);
    *(__half2*)(d + 12) = __floats2half2_rn(v3.x, v3.y);
    *(__half2*)(d + 14) = __floats2half2_rn(v3.z, v3.w);
}

__global__ __launch_bounds__(256) void convert_all_kernel(
    const float* __restrict__ spqkv, const float* __restrict__ spo,
    const float* __restrict__ tq, const float* __restrict__ tk,
    const float* __restrict__ tv, const float* __restrict__ to,
    const float* __restrict__ cqkv, const float* __restrict__ cwo,
    const float* __restrict__ m1, const float* __restrict__ m2)
{
    ll i = ((ll)blockIdx.x * 256 + threadIdx.x) * 16;
    if (i >= CONV_TOTAL) return;
    ll o = i;
    if (o < SEG_SPQKV) { cvt16(g_wspqkv + o, spqkv + o); return; }
    o -= SEG_SPQKV;
    if (o < SEG_DD)    { cvt16(g_wspo + o, spo + o); return; }
    o -= SEG_DD;
    if (o < SEG_DD) {
        ll e = o / SEG_CO, rem = o - e * SEG_CO;
        cvt16(g_wtpqkv + e * ((ll)D3*Dd) + rem, tq + o); return;
    }
    o -= SEG_DD;
    if (o < SEG_DD) {
        ll e = o / SEG_CO, rem = o - e * SEG_CO;
        cvt16(g_wtpqkv + e * ((ll)D3*Dd) + (ll)Dd*Dd + rem, tk + o); return;
    }
    o -= SEG_DD;
    if (o < SEG_DD) {
        ll e = o / SEG_CO, rem = o - e * SEG_CO;
        cvt16(g_wtpqkv + e * ((ll)D3*Dd) + (ll)2*Dd*Dd + rem, tv + o); return;
    }
    o -= SEG_DD;
    if (o < SEG_DD)   { cvt16(g_wtpo + o, to + o); return; }
    o -= SEG_DD;
    if (o < SEG_CQKV) { cvt16(g_wcqkv + o, cqkv + o); return; }
    o -= SEG_CQKV;
    if (o < SEG_CO)   { cvt16(g_wco + o, cwo + o); return; }
    o -= SEG_CO;
    if (o < SEG_M)    { cvt16(g_wm1 + o, m1 + o); return; }
    o -= SEG_M;
    cvt16(g_wm2 + o, m2 + o);
}

__global__ void pack_btp_kernel(const float* __restrict__ bq,
                                const float* __restrict__ bk,
                                const float* __restrict__ bv)
{
    int i = blockIdx.x * 256 + threadIdx.x;
    if (i >= NEXP * D3) return;
    int e = i / D3, j = i - e * D3;
    float v = (j < Dd) ? bq[e*Dd + j] : (j < 2*Dd) ? bk[e*Dd + j - Dd] : bv[e*Dd + j - 2*Dd];
    g_btp[i] = v;
}

// ---------------------------------------------------------------------------
// Router
// ---------------------------------------------------------------------------
__global__ void router_kernel(const float* __restrict__ x,
                              const float* __restrict__ w1, const float* __restrict__ b1,
                              const float* __restrict__ w2, const float* __restrict__ b2,
                              int* __restrict__ idx_s, int* __restrict__ idx_t)
{
    __shared__ float xm[Dd];
    __shared__ float hbuf[RH];
    __shared__ float lg[8];
    int b = blockIdx.x;
    int d = threadIdx.x;
    const float* xb = x + (ll)b * Tt * Dd;
    float s = 0.f;
    for (int t = 0; t < Tt; t++) s += xb[(ll)t * Dd + d];
    xm[d] = s * (1.0f / Tt);
    __syncthreads();
    if (d < RH) {
        float a = b1[d];
        const float* wr = w1 + (ll)d * Dd;
        for (int k = 0; k < Dd; k++) a += xm[k] * wr[k];
        hbuf[d] = gelu_exact(a);
    }
    __syncthreads();
    if (d < 8) {
        float a = b2[d];
        const float* wr = w2 + d * RH;
        for (int k = 0; k < RH; k++) a += hbuf[k] * wr[k];
        lg[d] = a;
    }
    __syncthreads();
    if (d == 0) {
        int is = 0; for (int i = 1; i < NEXP; i++) if (lg[i] > lg[is]) is = i;
        int it = 0; for (int i = 1; i < NEXP; i++) if (lg[NEXP+i] > lg[NEXP+it]) it = i;
        idx_s[b] = is;
        idx_t[b] = it;
    }
}

// ---------------------------------------------------------------------------
// Fused dual-output LayerNorm (validated R14)
// ---------------------------------------------------------------------------
__global__ __launch_bounds__(256) void ln_dual_kernel(const float* __restrict__ x,
    const float* __restrict__ g0, const float* __restrict__ b0,
    __half* __restrict__ yh0,
    const float* __restrict__ g1, const float* __restrict__ b1,
    __half* __restrict__ yh1, float* __restrict__ yf1)
{
    __shared__ float2 sw[8];
    ll row = blockIdx.x;
    int t = threadIdx.x, lane = t & 31, wid = t >> 5;
    const float* xr = x + row * Dd;
    float a0 = xr[t], a1 = xr[t+256], a2 = xr[t+512];
    float s = a0 + a1 + a2;
    float s2 = a0*a0 + a1*a1 + a2*a2;
    #pragma unroll
    for (int o = 16; o; o >>= 1) {
        s  += __shfl_xor_sync(0xFFFFFFFFu, s, o);
        s2 += __shfl_xor_sync(0xFFFFFFFFu, s2, o);
    }
    if (lane == 0) sw[wid] = make_float2(s, s2);
    __syncthreads();
    if (t < 8) {
        float2 v = sw[t];
        float u = v.x, u2 = v.y;
        #pragma unroll
        for (int o = 4; o; o >>= 1) {
            u  += __shfl_xor_sync(0xFFu, u, o);
            u2 += __shfl_xor_sync(0xFFu, u2, o);
        }
        if (t == 0) sw[0] = make_float2(u, u2);
    }
    __syncthreads();
    float2 tot = sw[0];
    float mean = tot.x * (1.0f / Dd);
    float var = tot.y * (1.0f / Dd) - mean * mean;
    float inv = rsqrtf(var + LN_EPS);
    float n0 = (a0 - mean) * inv;
    float n1 = (a1 - mean) * inv;
    float n2 = (a2 - mean) * inv;
    {
        float v0 = n0 * g0[t]     + b0[t];
        float v1 = n1 * g0[t+256] + b0[t+256];
        float v2 = n2 * g0[t+512] + b0[t+512];
        __half* yr = yh0 + row * Dd;
        yr[t]     = __float2half_rn(v0);
        yr[t+256] = __float2half_rn(v1);
        yr[t+512] = __float2half_rn(v2);
    }
    {
        float v0 = n0 * g1[t]     + b1[t];
        float v1 = n1 * g1[t+256] + b1[t+256];
        float v2 = n2 * g1[t+512] + b1[t+512];
        __half* yr = yh1 + row * Dd;
        yr[t]     = __float2half_rn(v0);
        yr[t+256] = __float2half_rn(v1);
        yr[t+512] = __float2half_rn(v2);
        float* yfr = yf1 + row * Dd;
        yfr[t] = v0; yfr[t+256] = v1; yfr[t+512] = v2;
    }
}

// Single-set LN (MLP)
__global__ __launch_bounds__(256) void ln_kernel(const float* __restrict__ x,
    const float* __restrict__ g, const float* __restrict__ bb,
    __half* __restrict__ yh)
{
    __shared__ float2 sw[8];
    ll row = blockIdx.x;
    int t = threadIdx.x, lane = t & 31, wid = t >> 5;
    const float* xr = x + row * Dd;
    float a0 = xr[t], a1 = xr[t+256], a2 = xr[t+512];
    float s = a0 + a1 + a2;
    float s2 = a0*a0 + a1*a1 + a2*a2;
    #pragma unroll
    for (int o = 16; o; o >>= 1) {
        s  += __shfl_xor_sync(0xFFFFFFFFu, s, o);
        s2 += __shfl_xor_sync(0xFFFFFFFFu, s2, o);
    }
    if (lane == 0) sw[wid] = make_float2(s, s2);
    __syncthreads();
    if (t < 8) {
        float2 v = sw[t];
        float u = v.x, u2 = v.y;
        #pragma unroll
        for (int o = 4; o; o >>= 1) {
            u  += __shfl_xor_sync(0xFFu, u, o);
            u2 += __shfl_xor_sync(0xFFu, u2, o);
        }
        if (t == 0) sw[0] = make_float2(u, u2);
    }
    __syncthreads();
    float2 tot = sw[0];
    float mean = tot.x * (1.0f / Dd);
    float var = tot.y * (1.0f / Dd) - mean * mean;
    float inv = rsqrtf(var + LN_EPS);
    __half* yr = yh + row * Dd;
    yr[t]     = __float2half_rn((a0 - mean) * inv * g[t]     + bb[t]);
    yr[t+256] = __float2half_rn((a1 - mean) * inv * g[t+256] + bb[t+256]);
    yr[t+512] = __float2half_rn((a2 - mean) * inv * g[t+512] + bb[t+512]);
}

// ---------------------------------------------------------------------------
// Flash attention (dual-set): Q pre-scaled at producer (validated R16)
// ---------------------------------------------------------------------------
#define FL_KLD  104
#define FL_TILE (128 * FL_KLD)
#define FL_TILEB (FL_TILE * 2)
#define FL_SMEM (3 * FL_TILEB)         // 79872

__device__ __forceinline__ void fl_load_tile(const __half* gbase, int row0,
                                             __half* dstsm, int cr, int cc)
{
    #pragma unroll
    for (int rp = 0; rp < 2; rp++) {
        int r = rp * 64 + cr;
        const __half* src = gbase + (ll)(row0 + r) * D3 + cc;
        uint32_t dst = smem_u32(dstsm) + (uint32_t)((r * FL_KLD + cc) * 2);
        CP_ASYNC_16(dst,      src);
        CP_ASYNC_16(dst + 16, src + 8);
        CP_ASYNC_16(dst + 32, src + 16);
    }
}

__global__ __launch_bounds__(256, 1) void flash_kernel(
    const __half* __restrict__ QKVa, __half* __restrict__ Oa, int causalA,
    const __half* __restrict__ QKVb, __half* __restrict__ Ob, int causalB)
{
    extern __shared__ __half fsm[];
    __half* Ksm = fsm;
    __half* Vsm = fsm + FL_TILE;

    int z = blockIdx.z;
    const __half* QKV; __half* O; int causal; int b;
    if (z < Bz) { QKV = QKVa; O = Oa; causal = causalA; b = z; }
    else        { QKV = QKVb; O = Ob; causal = causalB; b = z - Bz; }

    int qt = blockIdx.x, h = blockIdx.y;
    int q0 = qt * 128;
    int tid = threadIdx.x, lane = tid & 31, w = tid >> 5;
    int g = lane >> 2, t4 = lane & 3;

    const __half* Qg = QKV + (ll)b * (Tt * D3) + (ll)q0 * D3 + h * HD;
    const __half* Kg = QKV + (ll)b * (Tt * D3) + Dd + h * HD;
    const __half* Vg = Kg + Dd;

    int cr = tid >> 2;
    int cc = (tid & 3) * 24;

    #pragma unroll
    for (int rp = 0; rp < 2; rp++) {
        int r = rp * 64 + cr;
        const __half* src = Qg + (ll)r * D3 + cc;
        uint32_t dst = smem_u32(Ksm) + (uint32_t)((r * FL_KLD + cc) * 2);
        CP_ASYNC_16(dst,      src);
        CP_ASYNC_16(dst + 16, src + 8);
        CP_ASYNC_16(dst + 32, src + 16);
    }
    CP_COMMIT(); CP_WAIT(0);
    __syncthreads();

    uint32_t qfr[6][4];
    {
        uint32_t aBase = smem_u32(Ksm) +
            (uint32_t)(((((lane & 15) + w * 16)) * FL_KLD + ((lane >> 4) << 3)) * 2);
        #pragma unroll
        for (int ks = 0; ks < 6; ks++) ldsm_x4(qfr[ks], aBase + ks * 32);
    }
    __syncthreads();

    int nk = causal ? (q0 / 128 + 1) : (Tt / 128);

    fl_load_tile(Kg, 0, Ksm, cr, cc);
    fl_load_tile(Vg, 0, Vsm, cr, cc);
    CP_COMMIT();

    float mrow[2] = {-1e30f, -1e30f};
    float lrow[2] = {0.f, 0.f};
    float oacc[12][4];
    #pragma unroll
    for (int j = 0; j < 12; j++)
        #pragma unroll
        for (int q = 0; q < 4; q++) oacc[j][q] = 0.f;

    uint32_t kBase = smem_u32(Ksm) +
        (uint32_t)(((((lane & 7) + ((lane >> 4) << 3))) * FL_KLD + (((lane >> 3) & 1) << 3)) * 2);
    uint32_t vBase = smem_u32(Vsm) +
        (uint32_t)(((((lane & 7) + (((lane >> 3) & 1) << 3))) * FL_KLD + ((lane >> 4) << 3)) * 2);

    for (int kt = 0; kt < nk; kt++) {
        CP_WAIT(0);
        __syncthreads();
        int cur = kt & 1;

        float s[16][4];
        #pragma unroll
        for (int j = 0; j < 16; j++)
            #pragma unroll
            for (int q = 0; q < 4; q++) s[j][q] = 0.f;

        #pragma unroll
        for (int ks = 0; ks < 6; ks++) {
            #pragma unroll
            for (int jp = 0; jp < 8; jp++) {
                uint32_t rb[4];
                ldsm_x4(rb, kBase + jp * (16 * FL_KLD * 2) + ks * 32);
                mma_fp16(s[2*jp],   qfr[ks], rb);
                mma_fp16(s[2*jp+1], qfr[ks], rb + 2);
            }
        }

        bool domask = causal && (kt * 128 + 127 > q0);
        if (domask) {
            int rbase = q0 + w * 16 + g;
            #pragma unroll
            for (int j = 0; j < 16; j++) {
                int key0 = kt * 128 + j * 8 + 2 * t4;
                #pragma unroll
                for (int q = 0; q < 4; q++) {
                    int key = key0 + (q & 1);
                    int row = rbase + ((q >> 1) << 3);
                    if (key > row) s[j][q] = -1e30f;
                }
            }
        }

        uint32_t p[8][4];
        #pragma unroll
        for (int hf = 0; hf < 2; hf++) {
            float mx = -1e30f;
            #pragma unroll
            for (int j = 0; j < 16; j++)
                mx = fmaxf(mx, fmaxf(s[j][hf*2], s[j][hf*2+1]));
            mx = fmaxf(mx, __shfl_xor_sync(0xFFFFFFFFu, mx, 1));
            mx = fmaxf(mx, __shfl_xor_sync(0xFFFFFFFFu, mx, 2));
            float mnew = fmaxf(mrow[hf], mx);
            float corr = expf(mrow[hf] - mnew);
            mrow[hf] = mnew;
            float rsum = 0.f;
            #pragma unroll
            for (int j = 0; j < 16; j++) {
                float e0 = expf(s[j][hf*2]   - mnew);
                float e1 = expf(s[j][hf*2+1] - mnew);
                s[j][hf*2] = e0; s[j][hf*2+1] = e1;
                rsum += e0 + e1;
            }
            rsum += __shfl_xor_sync(0xFFFFFFFFu, rsum, 1);
            rsum += __shfl_xor_sync(0xFFFFFFFFu, rsum, 2);
            lrow[hf] = lrow[hf] * corr + rsum;
            #pragma unroll
            for (int j = 0; j < 12; j++) {
                oacc[j][hf*2]   *= corr;
                oacc[j][hf*2+1] *= corr;
            }
        }
        #pragma unroll
        for (int ksv = 0; ksv < 8; ksv++) {
            p[ksv][0] = packh2(s[2*ksv][0],   s[2*ksv][1]);
            p[ksv][1] = packh2(s[2*ksv][2],   s[2*ksv][3]);
            p[ksv][2] = packh2(s[2*ksv+1][0], s[2*ksv+1][1]);
            p[ksv][3] = packh2(s[2*ksv+1][2], s[2*ksv+1][3]);
        }

        __syncthreads();
        if (kt + 1 < nk) {
            fl_load_tile(Kg, (kt+1) * 128, Ksm, cr, cc);
            fl_load_tile(Vg, (kt+1) * 128, Vsm + (1 - cur) * FL_TILE, cr, cc);
            CP_COMMIT();
        }

        uint32_t vb = vBase + cur * FL_TILEB;
        #pragma unroll
        for (int ksv = 0; ksv < 8; ksv++) {
            #pragma unroll
            for (int jp = 0; jp < 6; jp++) {
                uint32_t rb[4];
                ldsm_x4_t(rb, vb + ksv * (16 * FL_KLD * 2) + jp * 32);
                mma_fp16(oacc[2*jp],   p[ksv], rb);
                mma_fp16(oacc[2*jp+1], p[ksv], rb + 2);
            }
        }
    }

    #pragma unroll
    for (int hf = 0; hf < 2; hf++) {
        float inv = 1.f / lrow[hf];
        int r = q0 + w * 16 + g + hf * 8;
        __half* orow = O + (ll)b * (Tt * Dd) + (ll)r * Dd + h * HD;
        #pragma unroll
        for (int j = 0; j < 12; j++) {
            *(__half2*)(orow + j * 8 + 2 * t4) =
                __floats2half2_rn(oacc[j][hf*2] * inv, oacc[j][hf*2+1] * inv);
        }
    }
}

// ---------------------------------------------------------------------------
// FP16 NT GEMM engine (exact R8 + qCols prescale; validated R16)
// ---------------------------------------------------------------------------
#define ALD   40
#define ASTG  (128 * ALD)
#define ASTGB (ASTG * 2)
#define GEMM_SMEM (2 * STAGES * ASTGB)   // 81920

struct GemmP {
    const __half* A;
    const __half* W;
    ll esW;
    const int* eidx;
    const float* bias;
    int esBias;
    const float* res;
    void* C;
    int ldc;
    int cHalf;
    int Kd;
    int act;
    int qCols;
};

__device__ __forceinline__ void gemm_body(const GemmP p, int b, int m0, int n0)
{
    extern __shared__ __half hsm[];
    __half* Asm = hsm;
    __half* Wsm = hsm + STAGES * ASTG;

    const __half* A = p.A + (ll)b * Tt * p.Kd;
    ll woff = 0;
    const float* biasp = p.bias;
    if (p.eidx) {
        int e = p.eidx[b];
        woff = (ll)e * p.esW;
        if (biasp) biasp += (ll)e * p.esBias;
    }
    const __half* W = p.W + woff;
    const float* res = p.res ? (p.res + (ll)b * (Tt * Dd)) : nullptr;

    int tid = threadIdx.x, lane = tid & 31, warp = tid >> 5;
    int wm = warp & 1, wn = warp >> 1;
    int wmb = wm * 64, wnb = wn * 64;
    int g = lane >> 2, t4 = lane & 3;

    int r0 = tid >> 2, c0 = (tid & 3) * 8;
    const __half* Ap = A + (ll)(m0 + r0) * p.Kd + c0;
    const __half* Wp = W + (ll)(n0 + r0) * p.Kd + c0;
    uint32_t dA = smem_u32(Asm) + (uint32_t)((r0 * ALD + c0) * 2);
    uint32_t dW = smem_u32(Wsm) + (uint32_t)((r0 * ALD + c0) * 2);
    ll rowStep = (ll)32 * p.Kd;

    float acc[4][8][4];
    #pragma unroll
    for (int i = 0; i < 4; i++)
        #pragma unroll
        for (int j = 0; j < 8; j++)
            #pragma unroll
            for (int q = 0; q < 4; q++) acc[i][j][q] = 0.f;

    uint32_t aBase = smem_u32(Asm) +
        (uint32_t)((((lane & 15) + wmb) * ALD + ((lane >> 4) << 3)) * 2);
    uint32_t bBase = smem_u32(Wsm) +
        (uint32_t)((((lane & 7) + ((lane >> 4) << 3) + wnb) * ALD + (((lane >> 3) & 1) << 3)) * 2);

    int kTiles = p.Kd >> 5;

    #pragma unroll
    for (int s = 0; s < STAGES - 1; s++) {
        if (s < kTiles) {
            const __half* a = Ap + s * 32;
            const __half* w = Wp + s * 32;
            #pragma unroll
            for (int rp = 0; rp < 4; rp++) {
                CP_ASYNC_16(dA + s * ASTGB + rp * (32 * ALD * 2), a + rp * rowStep);
                CP_ASYNC_16(dW + s * ASTGB + rp * (32 * ALD * 2), w + rp * rowStep);
            }
        }
        CP_COMMIT();
    }

    for (int kt = 0; kt < kTiles; kt++) {
        CP_WAIT(STAGES - 2);
        __syncthreads();

        int pf = kt + STAGES - 1;
        if (pf < kTiles) {
            int ps = pf & (STAGES - 1);
            const __half* a = Ap + pf * 32;
            const __half* w = Wp + pf * 32;
            #pragma unroll
            for (int rp = 0; rp < 4; rp++) {
                CP_ASYNC_16(dA + ps * ASTGB + rp * (32 * ALD * 2), a + rp * rowStep);
                CP_ASYNC_16(dW + ps * ASTGB + rp * (32 * ALD * 2), w + rp * rowStep);
            }
        }
        CP_COMMIT();

        uint32_t sa = aBase + (kt & (STAGES - 1)) * ASTGB;
        uint32_t sb = bBase + (kt & (STAGES - 1)) * ASTGB;
        #pragma unroll
        for (int ks = 0; ks < 2; ks++) {
            uint32_t afr[4][4], bfr[8][2];
            #pragma unroll
            for (int im = 0; im < 4; im++)
                ldsm_x4(afr[im], sa + im * (16 * ALD * 2) + ks * 32);
            #pragma unroll
            for (int jp = 0; jp < 4; jp++) {
                uint32_t rb[4];
                ldsm_x4(rb, sb + jp * (16 * ALD * 2) + ks * 32);
                bfr[2*jp][0]   = rb[0]; bfr[2*jp][1]   = rb[1];
                bfr[2*jp+1][0] = rb[2]; bfr[2*jp+1][1] = rb[3];
            }
            #pragma unroll
            for (int im = 0; im < 4; im++)
                #pragma unroll
                for (int jn = 0; jn < 8; jn++)
                    mma_fp16(acc[im][jn], afr[im], bfr[jn]);
        }
    }

    float alpha = (n0 < p.qCols) ? SCALE_V : 1.0f;

    __half* Ch = (__half*)p.C;
    float*  Cf = (float*)p.C;
    ll cb = (ll)b * Tt * p.ldc;
    #pragma unroll
    for (int im = 0; im < 4; im++) {
        int rr0 = m0 + wmb + im * 16 + g;
        #pragma unroll
        for (int jn = 0; jn < 8; jn++) {
            int c = n0 + wnb + jn * 8 + 2 * t4;
            float bv0 = biasp ? biasp[c]     : 0.f;
            float bv1 = biasp ? biasp[c + 1] : 0.f;
            #pragma unroll
            for (int hf = 0; hf < 2; hf++) {
                int r = rr0 + hf * 8;
                float v0 = (acc[im][jn][hf*2+0] + bv0) * alpha;
                float v1 = (acc[im][jn][hf*2+1] + bv1) * alpha;
                if (p.act) { v0 = gelu_exact(v0); v1 = gelu_exact(v1); }
                if (res) {
                    const float* rp2 = res + (ll)r * Dd + c;
                    v0 += rp2[0]; v1 += rp2[1];
                }
                if (p.cHalf)
                    *(__half2*)(Ch + cb + (ll)r * p.ldc + c) = __floats2half2_rn(v0, v1);
                else
                    *(float2*)(Cf + cb + (ll)r * p.ldc + c) = make_float2(v0, v1);
            }
        }
    }
}

__global__ __launch_bounds__(128, 2) void hgemm_one(GemmP p) {
    gemm_body(p, blockIdx.z, blockIdx.y * 128, blockIdx.x * 128);
}
__global__ __launch_bounds__(128, 2) void hgemm_dualz(GemmP p0, GemmP p1) {
    int z = blockIdx.z;
    if (z < Bz) gemm_body(p0, z, blockIdx.y * 128, blockIdx.x * 128);
    else        gemm_body(p1, z - Bz, blockIdx.y * 128, blockIdx.x * 128);
}
__global__ __launch_bounds__(128, 2) void hgemm_dualx(GemmP p0, GemmP p1, int xsplit) {
    int xb = blockIdx.x;
    if (xb < xsplit) gemm_body(p0, blockIdx.z, blockIdx.y * 128, xb * 128);
    else             gemm_body(p1, blockIdx.z, blockIdx.y * 128, (xb - xsplit) * 128);
}

// ---------------------------------------------------------------------------
// Orchestration (graph-parallel head: convert/pack on side stream,
// router+LN on main stream, fork/join via events)
// ---------------------------------------------------------------------------
extern "C" void kernel_launch(void* const* d_in, const int* in_sizes, int n_in,
                              void* d_out, int out_size)
{
    const float* x        = (const float*)d_in[0];
    const float* rw1      = (const float*)d_in[1];
    const float* rb1      = (const float*)d_in[2];
    const float* rw2      = (const float*)d_in[3];
    const float* rb2      = (const float*)d_in[4];
    const float* nsg      = (const float*)d_in[5];
    const float* nsb      = (const float*)d_in[6];
    const float* ntg      = (const float*)d_in[7];
    const float* ntb      = (const float*)d_in[8];
    const float* nmg      = (const float*)d_in[9];
    const float* nmb      = (const float*)d_in[10];
    const float* sp_wqkv  = (const float*)d_in[11];
    const float* sp_bqkv  = (const float*)d_in[12];
    const float* sp_wo    = (const float*)d_in[13];
    const float* sp_bo    = (const float*)d_in[14];
    const float* tp_wq    = (const float*)d_in[15];
    const float* tp_bq    = (const float*)d_in[16];
    const float* tp_wk    = (const float*)d_in[17];
    const float* tp_bk    = (const float*)d_in[18];
    const float* tp_wv    = (const float*)d_in[19];
    const float* tp_bv    = (const float*)d_in[20];
    const float* tp_wo    = (const float*)d_in[21];
    const float* tp_bo    = (const float*)d_in[22];
    const float* c_wqkv   = (const float*)d_in[23];
    const float* c_bqkv   = (const float*)d_in[24];
    const float* c_wo     = (const float*)d_in[25];
    const float* c_bo     = (const float*)d_in[26];
    const float* mlp_w1   = (const float*)d_in[27];
    const float* mlp_b1   = (const float*)d_in[28];
    const float* mlp_w2   = (const float*)d_in[29];
    const float* mlp_b2   = (const float*)d_in[30];
    float* out = (float*)d_out;

    static int init_done = 0;
    static cudaStream_t s2;
    static cudaEvent_t evFork, evJoin;
    if (!init_done) {
        cudaFuncSetAttribute(hgemm_one,   cudaFuncAttributeMaxDynamicSharedMemorySize, GEMM_SMEM);
        cudaFuncSetAttribute(hgemm_dualz, cudaFuncAttributeMaxDynamicSharedMemorySize, GEMM_SMEM);
        cudaFuncSetAttribute(hgemm_dualx, cudaFuncAttributeMaxDynamicSharedMemorySize, GEMM_SMEM);
        cudaFuncSetAttribute(flash_kernel, cudaFuncAttributeMaxDynamicSharedMemorySize, FL_SMEM);
        cudaStreamCreateWithFlags(&s2, cudaStreamNonBlocking);
        cudaEventCreateWithFlags(&evFork, cudaEventDisableTiming);
        cudaEventCreateWithFlags(&evJoin, cudaEventDisableTiming);
        init_done = 1;
    }

    float *xtf, *x1, *btp;
    __half *qkv, *qkv2, *xnh, *xth, *attno, *attno2, *spout, *tpout, *hid;
    __half *wspqkv, *wspo, *wtpqkv, *wtpo, *wcqkv, *wco, *wm1, *wm2;
    int* idx;
    cudaGetSymbolAddress((void**)&qkv,    g_qkvh);
    cudaGetSymbolAddress((void**)&qkv2,   g_qkv2h);
    cudaGetSymbolAddress((void**)&xnh,    g_xnh);
    cudaGetSymbolAddress((void**)&xth,    g_xth);
    cudaGetSymbolAddress((void**)&xtf,    g_xtf);
    cudaGetSymbolAddress((void**)&attno,  g_attno);
    cudaGetSymbolAddress((void**)&attno2, g_attno2);
    cudaGetSymbolAddress((void**)&spout,  g_spout);
    cudaGetSymbolAddress((void**)&tpout,  g_tpout);
    cudaGetSymbolAddress((void**)&x1,     g_x1);
    cudaGetSymbolAddress((void**)&hid,    g_hid);
    cudaGetSymbolAddress((void**)&idx,    g_idx);
    cudaGetSymbolAddress((void**)&btp,    g_btp);
    cudaGetSymbolAddress((void**)&wspqkv, g_wspqkv);
    cudaGetSymbolAddress((void**)&wspo,   g_wspo);
    cudaGetSymbolAddress((void**)&wtpqkv, g_wtpqkv);
    cudaGetSymbolAddress((void**)&wtpo,   g_wtpo);
    cudaGetSymbolAddress((void**)&wcqkv,  g_wcqkv);
    cudaGetSymbolAddress((void**)&wco,    g_wco);
    cudaGetSymbolAddress((void**)&wm1,    g_wm1);
    cudaGetSymbolAddress((void**)&wm2,    g_wm2);

    // ---- fork: weight conversion chain on s2, x-dependent chain on default ----
    cudaEventRecord(evFork, 0);
    cudaStreamWaitEvent(s2, evFork, 0);
    {
        int blocks = (int)((CONV_TOTAL / 16 + 255) / 256);
        convert_all_kernel<<<blocks, 256, 0, s2>>>(sp_wqkv, sp_wo, tp_wq, tp_wk, tp_wv,
                                                   tp_wo, c_wqkv, c_wo, mlp_w1, mlp_w2);
        pack_btp_kernel<<<(NEXP*D3 + 255)/256, 256, 0, s2>>>(tp_bq, tp_bk, tp_bv);
        cudaEventRecord(evJoin, s2);
    }
    router_kernel<<<Bz, Dd>>>(x, rw1, rb1, rw2, rb2, idx, idx + 8);
    ln_dual_kernel<<<4096, 256>>>(x, nsg, nsb, xnh, ntg, ntb, xth, xtf);
    cudaStreamWaitEvent(0, evJoin, 0);   // join before first GEMM

    // ---- QKV GEMMs (spatial + temporal fused; Q cols pre-scaled) ----
    {
        GemmP p0 = { xnh, wspqkv, (ll)D3 * Dd, idx,     sp_bqkv, D3, nullptr, qkv,  D3, 1, Dd, 0, Dd };
        GemmP p1 = { xth, wtpqkv, (ll)D3 * Dd, idx + 8, btp,     D3, nullptr, qkv2, D3, 1, Dd, 0, Dd };
        hgemm_dualz<<<dim3(D3/128, Tt/128, 2*Bz), 128, GEMM_SMEM>>>(p0, p1);
    }

    // ---- flash (spatial non-causal + temporal causal fused) ----
    flash_kernel<<<dim3(Tt/128, Hh, 2*Bz), 256, FL_SMEM>>>(qkv, attno, 0, qkv2, attno2, 1);

    // ---- output projections (spatial + temporal fused) ----
    {
        GemmP p0 = { attno,  wspo, (ll)Dd * Dd, idx,     sp_bo, Dd, nullptr, spout, Dd, 1, Dd, 0, 0 };
        GemmP p1 = { attno2, wtpo, (ll)Dd * Dd, idx + 8, tp_bo, Dd, xtf,     tpout, Dd, 1, Dd, 0, 0 };
        hgemm_dualz<<<dim3(Dd/128, Tt/128, 2*Bz), 128, GEMM_SMEM>>>(p0, p1);
    }

    // ---- cross q (from spout; pre-scaled) + cross kv (from tpout) ----
    {
        GemmP p0 = { spout, wcqkv,                0, nullptr, c_bqkv,      0, nullptr, qkv,      D3, 1, Dd, 0, Dd };
        GemmP p1 = { tpout, wcqkv + (ll)Dd * Dd,  0, nullptr, c_bqkv + Dd, 0, nullptr, qkv + Dd, D3, 1, Dd, 0, 0 };
        hgemm_dualx<<<dim3(18, Tt/128, Bz), 128, GEMM_SMEM>>>(p0, p1, 6);
    }

    // ---- cross flash ----
    flash_kernel<<<dim3(Tt/128, Hh, Bz), 256, FL_SMEM>>>(qkv, attno, 0, qkv, attno, 0);

    // ---- cross out: x1 = x + attno @ wco^T + c_bo (fp32) ----
    {
        GemmP p = { attno, wco, 0, nullptr, c_bo, 0, x, x1, Dd, 0, Dd, 0, 0 };
        hgemm_one<<<dim3(Dd/128, Tt/128, Bz), 128, GEMM_SMEM>>>(p);
    }

    // ---- MLP ----
    ln_kernel<<<4096, 256>>>(x1, nmg, nmb, xnh);

    {
        GemmP p = { xnh, wm1, 0, nullptr, mlp_b1, 0, nullptr, hid, D4, 1, Dd, 1, 0 };
        hgemm_one<<<dim3(D4/128, (Bz*Tt)/128, 1), 128, GEMM_SMEM>>>(p);
    }
    {
        GemmP p = { hid, wm2, 0, nullptr, mlp_b2, 0, x1, out, Dd, 0, D4, 0, 0 };
        hgemm_one<<<dim3(Dd/128, (Bz*Tt)/128, 1), 128, GEMM_SMEM>>>(p);
    }
}